// round 1
// baseline (speedup 1.0000x reference)
#include <cuda_runtime.h>
#include <cuda_bf16.h>
#include <mma.h>
#include <math.h>

using namespace nvcuda;

#define T0B 4
#define T0N 1370
#define T1B 8
#define T1N 257
#define TTOT (T0B*T0N + T1B*T1N)   /* 7536 */
#define DIM 1024
#define NH 16
#define DH 64
#define HID 4096
#define QKVW (3*DIM)

// ---------------- scratch (static device globals; no allocation) ----------------
__device__ float g_x[TTOT*DIM];
__device__ float g_lnx[TTOT*DIM];
__device__ float g_qkv[(size_t)TTOT*QKVW];
__device__ float g_att[TTOT*DIM];
__device__ float g_h[TTOT*DIM];
__device__ float g_ln2[TTOT*DIM];
__device__ float g_fc1[(size_t)TTOT*HID];

// ---------------- helpers ----------------
__device__ __forceinline__ float2 ffma2(float2 a, float2 b, float2 c) {
    float2 d;
    asm("fma.rn.f32x2 %0, %1, %2, %3;"
        : "=l"(reinterpret_cast<unsigned long long&>(d))
        : "l"(reinterpret_cast<unsigned long long&>(a)),
          "l"(reinterpret_cast<unsigned long long&>(b)),
          "l"(reinterpret_cast<unsigned long long&>(c)));
    return d;
}

__device__ __forceinline__ float gelu_exact(float x) {
    return 0.5f * x * (1.0f + erff(x * 0.70710678118654752f));
}

// ---------------- pack x0,x1 -> g_x ----------------
__global__ void pack_x(const float* __restrict__ x0, const float* __restrict__ x1) {
    size_t i = (size_t)blockIdx.x * 256 + threadIdx.x;   // float4 index
    size_t n4 = (size_t)TTOT * DIM / 4;
    if (i >= n4) return;
    size_t e = i * 4;
    size_t split = (size_t)T0B * T0N * DIM;
    float4 v = (e < split) ? reinterpret_cast<const float4*>(x0)[i]
                           : reinterpret_cast<const float4*>(x1)[(e - split) >> 2];
    reinterpret_cast<float4*>(g_x)[i] = v;
}

// ---------------- layernorm (row per block, 256 threads, 4 f32/thread) ----------------
__global__ void ln_kernel(const float* __restrict__ in, const float* __restrict__ gw,
                          const float* __restrict__ bw, float* __restrict__ out) {
    int row = blockIdx.x;
    int tid = threadIdx.x;
    const float4 v = reinterpret_cast<const float4*>(in + (size_t)row * DIM)[tid];
    float s  = v.x + v.y + v.z + v.w;
    float s2 = v.x*v.x + v.y*v.y + v.z*v.z + v.w*v.w;
    #pragma unroll
    for (int o = 16; o; o >>= 1) {
        s  += __shfl_down_sync(0xffffffffu, s,  o);
        s2 += __shfl_down_sync(0xffffffffu, s2, o);
    }
    __shared__ float ss[8], ss2[8];
    __shared__ float mb, rb;
    int w = tid >> 5, l = tid & 31;
    if (l == 0) { ss[w] = s; ss2[w] = s2; }
    __syncthreads();
    if (tid == 0) {
        float a = 0.f, a2 = 0.f;
        #pragma unroll
        for (int i = 0; i < 8; i++) { a += ss[i]; a2 += ss2[i]; }
        float m = a * (1.0f / DIM);
        float var = a2 * (1.0f / DIM) - m * m;
        mb = m;
        rb = rsqrtf(var + 1e-5f);
    }
    __syncthreads();
    float m = mb, r = rb;
    float4 g4 = reinterpret_cast<const float4*>(gw)[tid];
    float4 b4 = reinterpret_cast<const float4*>(bw)[tid];
    float4 o;
    o.x = (v.x - m) * r * g4.x + b4.x;
    o.y = (v.y - m) * r * g4.y + b4.y;
    o.z = (v.z - m) * r * g4.z + b4.z;
    o.w = (v.w - m) * r * g4.w + b4.w;
    reinterpret_cast<float4*>(out + (size_t)row * DIM)[tid] = o;
}

// ---------------- bf16 wmma GEMM: C = epi(A[MxK] * B[KxN] + bias) ----------------
// MODE 0: C = AB + bias
// MODE 1: C = res + ls * (AB + bias)
// MODE 2: C = gelu(AB + bias)
#define BM 128
#define BN 128
#define BK 32
#define APAD 48
#define BPAD 136
#define CPAD 132
#define GEMM_SMEM (BM*CPAD*4)   /* 67584; > A/B stage (BM*APAD+BK*BPAD)*2=20992 */

template<int MODE>
__global__ __launch_bounds__(256, 1)
void gemm_kernel(const float* __restrict__ A, const float* __restrict__ B,
                 const float* __restrict__ bias, const float* __restrict__ res,
                 const float* __restrict__ ls, float* __restrict__ C,
                 int M, int N, int K) {
    extern __shared__ char smem[];
    __nv_bfloat16* As = reinterpret_cast<__nv_bfloat16*>(smem);  // [BM][APAD]
    __nv_bfloat16* Bs = As + BM * APAD;                           // [BK][BPAD]
    float* Cs = reinterpret_cast<float*>(smem);                   // [BM][CPAD] (reused)

    int tid = threadIdx.x;
    int wid = tid >> 5, lane = tid & 31;
    int m0 = blockIdx.x * BM, n0 = blockIdx.y * BN;
    int wr = wid >> 2, wc = wid & 3;   // warp tile origin (wr*64, wc*32)

    wmma::fragment<wmma::accumulator, 16, 16, 16, float> acc[4][2];
    #pragma unroll
    for (int i = 0; i < 4; i++)
        #pragma unroll
        for (int j = 0; j < 2; j++)
            wmma::fill_fragment(acc[i][j], 0.0f);

    int arow = tid >> 3,  acol = (tid & 7) * 4;   // + p*32 rows
    int brow = tid >> 5,  bcol = (tid & 31) * 4;  // + p*8  rows

    float4 aReg[4], bReg[4];
    int nk = K / BK;

    // prefetch tile 0
    #pragma unroll
    for (int p = 0; p < 4; p++) {
        int r = m0 + arow + p * 32;
        aReg[p] = (r < M) ? *reinterpret_cast<const float4*>(A + (size_t)r * K + acol)
                          : make_float4(0.f, 0.f, 0.f, 0.f);
    }
    #pragma unroll
    for (int p = 0; p < 4; p++) {
        int r = brow + p * 8;
        bReg[p] = *reinterpret_cast<const float4*>(B + (size_t)r * N + n0 + bcol);
    }

    for (int kt = 0; kt < nk; ++kt) {
        // stage regs -> smem (fp32 -> bf16)
        #pragma unroll
        for (int p = 0; p < 4; p++) {
            __nv_bfloat16* d = As + (arow + p * 32) * APAD + acol;
            d[0] = __float2bfloat16(aReg[p].x);
            d[1] = __float2bfloat16(aReg[p].y);
            d[2] = __float2bfloat16(aReg[p].z);
            d[3] = __float2bfloat16(aReg[p].w);
        }
        #pragma unroll
        for (int p = 0; p < 4; p++) {
            __nv_bfloat16* d = Bs + (brow + p * 8) * BPAD + bcol;
            d[0] = __float2bfloat16(bReg[p].x);
            d[1] = __float2bfloat16(bReg[p].y);
            d[2] = __float2bfloat16(bReg[p].z);
            d[3] = __float2bfloat16(bReg[p].w);
        }
        __syncthreads();

        // prefetch next tile (LDGs overlap with MMA below)
        if (kt + 1 < nk) {
            int kb = (kt + 1) * BK;
            #pragma unroll
            for (int p = 0; p < 4; p++) {
                int r = m0 + arow + p * 32;
                aReg[p] = (r < M) ? *reinterpret_cast<const float4*>(A + (size_t)r * K + kb + acol)
                                  : make_float4(0.f, 0.f, 0.f, 0.f);
            }
            #pragma unroll
            for (int p = 0; p < 4; p++) {
                int r = kb + brow + p * 8;
                bReg[p] = *reinterpret_cast<const float4*>(B + (size_t)r * N + n0 + bcol);
            }
        }

        #pragma unroll
        for (int ks = 0; ks < 2; ++ks) {
            wmma::fragment<wmma::matrix_a, 16, 16, 16, __nv_bfloat16, wmma::row_major> af[4];
            wmma::fragment<wmma::matrix_b, 16, 16, 16, __nv_bfloat16, wmma::row_major> bfm[2];
            #pragma unroll
            for (int i = 0; i < 4; i++)
                wmma::load_matrix_sync(af[i], As + (wr * 64 + i * 16) * APAD + ks * 16, APAD);
            #pragma unroll
            for (int j = 0; j < 2; j++)
                wmma::load_matrix_sync(bfm[j], Bs + (ks * 16) * BPAD + wc * 32 + j * 16, BPAD);
            #pragma unroll
            for (int i = 0; i < 4; i++)
                #pragma unroll
                for (int j = 0; j < 2; j++)
                    wmma::mma_sync(acc[i][j], af[i], bfm[j], acc[i][j]);
        }
        __syncthreads();
    }

    // epilogue: stage acc in smem, then coalesced fused writeback
    #pragma unroll
    for (int i = 0; i < 4; i++)
        #pragma unroll
        for (int j = 0; j < 2; j++)
            wmma::store_matrix_sync(Cs + (wr * 64 + i * 16) * CPAD + wc * 32 + j * 16,
                                    acc[i][j], CPAD, wmma::mem_row_major);
    __syncthreads();

    #pragma unroll
    for (int it = 0; it < 16; ++it) {
        int r = wid + it * 8;
        int c = lane * 4;
        int gr = m0 + r, gc = n0 + c;
        if (gr < M) {
            float4 v = *reinterpret_cast<float4*>(Cs + r * CPAD + c);
            float4 bb = *reinterpret_cast<const float4*>(bias + gc);
            v.x += bb.x; v.y += bb.y; v.z += bb.z; v.w += bb.w;
            if (MODE == 1) {
                float4 rr = *reinterpret_cast<const float4*>(res + (size_t)gr * N + gc);
                float4 lv = *reinterpret_cast<const float4*>(ls + gc);
                v.x = rr.x + lv.x * v.x;
                v.y = rr.y + lv.y * v.y;
                v.z = rr.z + lv.z * v.z;
                v.w = rr.w + lv.w * v.w;
            } else if (MODE == 2) {
                v.x = gelu_exact(v.x);
                v.y = gelu_exact(v.y);
                v.z = gelu_exact(v.z);
                v.w = gelu_exact(v.w);
            }
            *reinterpret_cast<float4*>(C + (size_t)gr * N + gc) = v;
        }
    }
}

// ---------------- flash attention: per (qtile, head, sample) block ----------------
// smem: qs/ks/vs each [64][33] float2 (dims packed in pairs; pad avoids conflicts)
#define ATTN_SMEM (3*64*33*8)   /* 50688 */

__global__ __launch_bounds__(256, 1)
void attn_kernel(int tok_off, int n) {
    extern __shared__ float2 sm2[];
    float2* qs = sm2;
    float2* ks = sm2 + 64 * 33;
    float2* vs = sm2 + 2 * 64 * 33;

    int b = blockIdx.z, h = blockIdx.y;
    int q0 = blockIdx.x * 64;
    int base = tok_off + b * n;
    int tid = threadIdx.x, wid = tid >> 5, lane = tid & 31;

    // load + scale Q tile
    for (int i = tid; i < 64 * 32; i += 256) {
        int r = i >> 5, d2 = i & 31;
        float2 v = make_float2(0.f, 0.f);
        if (q0 + r < n) {
            v = *reinterpret_cast<const float2*>(
                    g_qkv + (size_t)(base + q0 + r) * QKVW + h * DH + d2 * 2);
            v.x *= 0.125f; v.y *= 0.125f;
        }
        qs[r * 33 + d2] = v;
    }

    float mrow[8], lrow[8];
    float2 acc[8];
    #pragma unroll
    for (int rr = 0; rr < 8; rr++) { mrow[rr] = -1e30f; lrow[rr] = 0.f; acc[rr] = make_float2(0.f, 0.f); }

    int nchunks = (n + 63) >> 6;
    for (int kc = 0; kc < nchunks; ++kc) {
        __syncthreads();
        int kbase = kc * 64;
        int kcnt = min(64, n - kbase);
        for (int i = tid; i < 64 * 32; i += 256) {
            int r = i >> 5, d2 = i & 31;
            float2 kv = make_float2(0.f, 0.f), vv = make_float2(0.f, 0.f);
            if (r < kcnt) {
                size_t o = (size_t)(base + kbase + r) * QKVW + h * DH + d2 * 2;
                kv = *reinterpret_cast<const float2*>(g_qkv + DIM + o);
                vv = *reinterpret_cast<const float2*>(g_qkv + 2 * DIM + o);
            }
            ks[r * 33 + d2] = kv;
            vs[r * 33 + d2] = vv;
        }
        __syncthreads();

        #pragma unroll 1
        for (int rr = 0; rr < 8; ++rr) {
            int row = wid * 8 + rr;
            const float2* qp  = qs + row * 33;
            const float2* kp0 = ks + lane * 33;
            const float2* kp1 = ks + (lane + 32) * 33;
            float2 a0 = make_float2(0.f, 0.f), a1 = make_float2(0.f, 0.f);
            #pragma unroll
            for (int d2 = 0; d2 < 32; ++d2) {
                float2 q = qp[d2];
                a0 = ffma2(q, kp0[d2], a0);
                a1 = ffma2(q, kp1[d2], a1);
            }
            float s0 = a0.x + a0.y;
            float s1 = a1.x + a1.y;
            if (lane >= kcnt)      s0 = -1e30f;
            if (lane + 32 >= kcnt) s1 = -1e30f;
            float mx = fmaxf(s0, s1);
            #pragma unroll
            for (int o = 16; o; o >>= 1) mx = fmaxf(mx, __shfl_xor_sync(0xffffffffu, mx, o));
            float mnew = fmaxf(mrow[rr], mx);
            float p0 = __expf(s0 - mnew);
            float p1 = __expf(s1 - mnew);
            float ps = p0 + p1;
            #pragma unroll
            for (int o = 16; o; o >>= 1) ps += __shfl_xor_sync(0xffffffffu, ps, o);
            float corr = __expf(mrow[rr] - mnew);
            lrow[rr] = lrow[rr] * corr + ps;
            float2 a = acc[rr];
            a.x *= corr; a.y *= corr;
            #pragma unroll
            for (int k = 0; k < 32; k++) {
                float pk0 = __shfl_sync(0xffffffffu, p0, k);
                float pk1 = __shfl_sync(0xffffffffu, p1, k);
                a = ffma2(make_float2(pk0, pk0), vs[k * 33 + lane], a);
                a = ffma2(make_float2(pk1, pk1), vs[(k + 32) * 33 + lane], a);
            }
            acc[rr] = a;
            mrow[rr] = mnew;
        }
    }

    #pragma unroll
    for (int rr = 0; rr < 8; rr++) {
        int row = wid * 8 + rr;
        if (q0 + row < n) {
            float inv = 1.0f / lrow[rr];
            float2 o = make_float2(acc[rr].x * inv, acc[rr].y * inv);
            *reinterpret_cast<float2*>(
                g_att + (size_t)(base + q0 + row) * DIM + h * DH + lane * 2) = o;
        }
    }
}

// ---------------- host launcher ----------------
extern "C" void kernel_launch(void* const* d_in, const int* in_sizes, int n_in,
                              void* d_out, int out_size) {
    const float* x0     = (const float*)d_in[0];
    const float* x1     = (const float*)d_in[1];
    const float* ln1_g  = (const float*)d_in[2];
    const float* ln1_b  = (const float*)d_in[3];
    const float* qkv_w  = (const float*)d_in[4];
    const float* qkv_b  = (const float*)d_in[5];
    const float* proj_w = (const float*)d_in[6];
    const float* proj_b = (const float*)d_in[7];
    const float* ls1    = (const float*)d_in[8];
    const float* ln2_g  = (const float*)d_in[9];
    const float* ln2_b  = (const float*)d_in[10];
    const float* fc1_w  = (const float*)d_in[11];
    const float* fc1_b  = (const float*)d_in[12];
    const float* fc2_w  = (const float*)d_in[13];
    const float* fc2_b  = (const float*)d_in[14];
    const float* ls2    = (const float*)d_in[15];
    float* out = (float*)d_out;

    float *px, *plnx, *pqkv, *patt, *ph, *pln2, *pfc1;
    cudaGetSymbolAddress((void**)&px,   g_x);
    cudaGetSymbolAddress((void**)&plnx, g_lnx);
    cudaGetSymbolAddress((void**)&pqkv, g_qkv);
    cudaGetSymbolAddress((void**)&patt, g_att);
    cudaGetSymbolAddress((void**)&ph,   g_h);
    cudaGetSymbolAddress((void**)&pln2, g_ln2);
    cudaGetSymbolAddress((void**)&pfc1, g_fc1);

    cudaFuncSetAttribute(gemm_kernel<0>, cudaFuncAttributeMaxDynamicSharedMemorySize, GEMM_SMEM);
    cudaFuncSetAttribute(gemm_kernel<1>, cudaFuncAttributeMaxDynamicSharedMemorySize, GEMM_SMEM);
    cudaFuncSetAttribute(gemm_kernel<2>, cudaFuncAttributeMaxDynamicSharedMemorySize, GEMM_SMEM);
    cudaFuncSetAttribute(attn_kernel,    cudaFuncAttributeMaxDynamicSharedMemorySize, ATTN_SMEM);

    const int mtiles = (TTOT + BM - 1) / BM;  // 59

    // 1. pack x
    pack_x<<<(TTOT * DIM / 4 + 255) / 256, 256>>>(x0, x1);
    // 2. LN1
    ln_kernel<<<TTOT, 256>>>(px, ln1_g, ln1_b, plnx);
    // 3. QKV gemm: [T,1024]x[1024,3072]
    gemm_kernel<0><<<dim3(mtiles, QKVW / BN), 256, GEMM_SMEM>>>(
        plnx, qkv_w, qkv_b, nullptr, nullptr, pqkv, TTOT, QKVW, DIM);
    // 4. attention (per ragged group)
    attn_kernel<<<dim3((T0N + 63) / 64, NH, T0B), 256, ATTN_SMEM>>>(0, T0N);
    attn_kernel<<<dim3((T1N + 63) / 64, NH, T1B), 256, ATTN_SMEM>>>(T0B * T0N, T1N);
    // 5. proj gemm + residual: h = x + ls1*(att @ proj_w + b)
    gemm_kernel<1><<<dim3(mtiles, DIM / BN), 256, GEMM_SMEM>>>(
        patt, proj_w, proj_b, px, ls1, ph, TTOT, DIM, DIM);
    // 6. LN2
    ln_kernel<<<TTOT, 256>>>(ph, ln2_g, ln2_b, pln2);
    // 7. fc1 gemm + gelu
    gemm_kernel<2><<<dim3(mtiles, HID / BN), 256, GEMM_SMEM>>>(
        pln2, fc1_w, fc1_b, nullptr, nullptr, pfc1, TTOT, HID, DIM);
    // 8. fc2 gemm + residual -> out
    gemm_kernel<1><<<dim3(mtiles, DIM / BN), 256, GEMM_SMEM>>>(
        pfc1, fc2_w, fc2_b, ph, ls2, out, TTOT, DIM, HID);
}

// round 2
// speedup vs baseline: 2.7678x; 2.7678x over previous
#include <cuda_runtime.h>
#include <cuda_bf16.h>
#include <mma.h>
#include <math.h>

using namespace nvcuda;

#define T0B 4
#define T0N 1370
#define T1B 8
#define T1N 257
#define TTOT (T0B*T0N + T1B*T1N)   /* 7536 */
#define DIM 1024
#define NH 16
#define DH 64
#define HID 4096
#define QKVW (3*DIM)

typedef __nv_bfloat16 bf16;
typedef __nv_bfloat162 bf162;

// ---------------- scratch (static device globals; no allocation) ----------------
__device__ float g_x[TTOT*DIM];                    // packed input (residual 1)
__device__ float g_h[TTOT*DIM];                    // residual 2
__device__ bf16  g_lnx[TTOT*DIM];
__device__ bf16  g_qkv[(size_t)TTOT*QKVW];
__device__ bf16  g_att[TTOT*DIM];
__device__ bf16  g_ln2[TTOT*DIM];
__device__ bf16  g_fc1[(size_t)TTOT*HID];
__device__ bf16  g_qkvw[DIM*QKVW];
__device__ bf16  g_projw[DIM*DIM];
__device__ bf16  g_fc1w[DIM*HID];
__device__ bf16  g_fc2w[HID*DIM];

// ---------------- helpers ----------------
__device__ __forceinline__ float gelu_exact(float x) {
    return 0.5f * x * (1.0f + erff(x * 0.70710678118654752f));
}
__device__ __forceinline__ unsigned smem_u32(const void* p) {
    return (unsigned)__cvta_generic_to_shared(p);
}
#define CP_ASYNC16(dst, src) \
    asm volatile("cp.async.cg.shared.global [%0], [%1], 16;\n" :: "r"(dst), "l"(src))
#define CP_COMMIT() asm volatile("cp.async.commit_group;\n" ::: "memory")
#define CP_WAIT(N)  asm volatile("cp.async.wait_group %0;\n" :: "n"(N) : "memory")

__device__ __forceinline__ void store4(float* C, size_t idx, float4 v) {
    *reinterpret_cast<float4*>(C + idx) = v;
}
__device__ __forceinline__ void store4(bf16* C, size_t idx, float4 v) {
    bf162 lo = __halves2bfloat162(__float2bfloat16(v.x), __float2bfloat16(v.y));
    bf162 hi = __halves2bfloat162(__float2bfloat16(v.z), __float2bfloat16(v.w));
    uint2 u;
    u.x = *reinterpret_cast<unsigned*>(&lo);
    u.y = *reinterpret_cast<unsigned*>(&hi);
    *reinterpret_cast<uint2*>(C + idx) = u;
}

// ---------------- pack x0,x1 -> g_x ----------------
__global__ void pack_x(const float* __restrict__ x0, const float* __restrict__ x1) {
    size_t i = (size_t)blockIdx.x * 256 + threadIdx.x;
    size_t n4 = (size_t)TTOT * DIM / 4;
    if (i >= n4) return;
    size_t e = i * 4;
    size_t split = (size_t)T0B * T0N * DIM;
    float4 v = (e < split) ? reinterpret_cast<const float4*>(x0)[i]
                           : reinterpret_cast<const float4*>(x1)[(e - split) >> 2];
    reinterpret_cast<float4*>(g_x)[i] = v;
}

// ---------------- f32 -> bf16 weight convert ----------------
__global__ void cvt_kernel(const float* __restrict__ in, bf16* __restrict__ out, int n4) {
    int i = blockIdx.x * 256 + threadIdx.x;
    if (i >= n4) return;
    float4 v = reinterpret_cast<const float4*>(in)[i];
    store4(out, (size_t)i * 4, v);
}

// ---------------- layernorm: fp32 in -> bf16 out ----------------
__global__ void ln_kernel(const float* __restrict__ in, const float* __restrict__ gw,
                          const float* __restrict__ bw, bf16* __restrict__ out) {
    int row = blockIdx.x;
    int tid = threadIdx.x;
    const float4 v = reinterpret_cast<const float4*>(in + (size_t)row * DIM)[tid];
    float s  = v.x + v.y + v.z + v.w;
    float s2 = v.x*v.x + v.y*v.y + v.z*v.z + v.w*v.w;
    #pragma unroll
    for (int o = 16; o; o >>= 1) {
        s  += __shfl_down_sync(0xffffffffu, s,  o);
        s2 += __shfl_down_sync(0xffffffffu, s2, o);
    }
    __shared__ float ss[8], ss2[8];
    __shared__ float mb, rb;
    int w = tid >> 5, l = tid & 31;
    if (l == 0) { ss[w] = s; ss2[w] = s2; }
    __syncthreads();
    if (tid == 0) {
        float a = 0.f, a2 = 0.f;
        #pragma unroll
        for (int i = 0; i < 8; i++) { a += ss[i]; a2 += ss2[i]; }
        float m = a * (1.0f / DIM);
        float var = a2 * (1.0f / DIM) - m * m;
        mb = m;
        rb = rsqrtf(var + 1e-5f);
    }
    __syncthreads();
    float m = mb, r = rb;
    float4 g4 = reinterpret_cast<const float4*>(gw)[tid];
    float4 b4 = reinterpret_cast<const float4*>(bw)[tid];
    float4 o;
    o.x = (v.x - m) * r * g4.x + b4.x;
    o.y = (v.y - m) * r * g4.y + b4.y;
    o.z = (v.z - m) * r * g4.z + b4.z;
    o.w = (v.w - m) * r * g4.w + b4.w;
    store4(out, (size_t)row * DIM + tid * 4, o);
}

// ---------------- bf16 wmma GEMM, cp.async double-buffered ----------------
// MODE 0: C = AB + bias         MODE 1: C = res + ls*(AB+bias)    MODE 2: C = gelu(AB+bias)
#define BM 128
#define BN 128
#define BK 64
#define ASTR 72
#define BSTR 136
#define A_BYTES (BM*ASTR*2)    /* 18432 */
#define B_BYTES (BK*BSTR*2)    /* 17408 */
#define STAGE_BYTES (A_BYTES + B_BYTES)   /* 35840 */
#define CPAD 132
#define GEMM_SMEM (2*STAGE_BYTES)  /* 71680 > Cs(128*132*4=67584) */

template<int MODE, typename OT>
__global__ __launch_bounds__(256, 1)
void gemm_kernel(const bf16* __restrict__ A, const bf16* __restrict__ B,
                 const float* __restrict__ bias, const float* __restrict__ res,
                 const float* __restrict__ ls, OT* __restrict__ C,
                 int M, int N, int K) {
    extern __shared__ char smem[];
    int tid = threadIdx.x;
    int wid = tid >> 5, lane = tid & 31;
    int m0 = blockIdx.x * BM, n0 = blockIdx.y * BN;
    int wr = wid >> 2, wc = wid & 3;   // warp tile (wr*64 rows, wc*32 cols)

    wmma::fragment<wmma::accumulator, 16, 16, 16, float> acc[4][2];
    #pragma unroll
    for (int i = 0; i < 4; i++)
        #pragma unroll
        for (int j = 0; j < 2; j++)
            wmma::fill_fragment(acc[i][j], 0.0f);

    int nk = K / BK;

    // per-thread load coords
    int aRow0 = tid >> 1;            // i = tid + k*256: row = i>>3? recompute inline
    (void)aRow0;

    auto load_stage = [&](int kt) {
        char* As = smem + (kt & 1) * STAGE_BYTES;
        char* Bs = As + A_BYTES;
        // A tile: 128 rows x 64 cols -> 1024 16B chunks, 4/thread
        #pragma unroll
        for (int k = 0; k < 4; k++) {
            int i = tid + k * 256;
            int row = i >> 3, c8 = i & 7;
            int grow = m0 + row; if (grow >= M) grow = M - 1;
            const bf16* src = A + (size_t)grow * K + kt * BK + c8 * 8;
            unsigned dst = smem_u32(As + row * (ASTR * 2) + c8 * 16);
            CP_ASYNC16(dst, src);
        }
        // B tile: 64 rows x 128 cols -> 1024 16B chunks, 4/thread
        #pragma unroll
        for (int k = 0; k < 4; k++) {
            int i = tid + k * 256;
            int row = i >> 4, c8 = i & 15;
            const bf16* src = B + (size_t)(kt * BK + row) * N + n0 + c8 * 8;
            unsigned dst = smem_u32(Bs + row * (BSTR * 2) + c8 * 16);
            CP_ASYNC16(dst, src);
        }
        CP_COMMIT();
    };

    load_stage(0);

    for (int kt = 0; kt < nk; ++kt) {
        if (kt + 1 < nk) { load_stage(kt + 1); CP_WAIT(1); }
        else             { CP_WAIT(0); }
        __syncthreads();

        bf16* As = reinterpret_cast<bf16*>(smem + (kt & 1) * STAGE_BYTES);
        bf16* Bs = reinterpret_cast<bf16*>(smem + (kt & 1) * STAGE_BYTES + A_BYTES);

        #pragma unroll
        for (int ks = 0; ks < 4; ++ks) {
            wmma::fragment<wmma::matrix_a, 16, 16, 16, bf16, wmma::row_major> af[4];
            wmma::fragment<wmma::matrix_b, 16, 16, 16, bf16, wmma::row_major> bfm[2];
            #pragma unroll
            for (int i = 0; i < 4; i++)
                wmma::load_matrix_sync(af[i], As + (wr * 64 + i * 16) * ASTR + ks * 16, ASTR);
            #pragma unroll
            for (int j = 0; j < 2; j++)
                wmma::load_matrix_sync(bfm[j], Bs + (ks * 16) * BSTR + wc * 32 + j * 16, BSTR);
            #pragma unroll
            for (int i = 0; i < 4; i++)
                #pragma unroll
                for (int j = 0; j < 2; j++)
                    wmma::mma_sync(acc[i][j], af[i], bfm[j], acc[i][j]);
        }
        __syncthreads();
    }

    // epilogue via smem
    float* Cs = reinterpret_cast<float*>(smem);
    #pragma unroll
    for (int i = 0; i < 4; i++)
        #pragma unroll
        for (int j = 0; j < 2; j++)
            wmma::store_matrix_sync(Cs + (wr * 64 + i * 16) * CPAD + wc * 32 + j * 16,
                                    acc[i][j], CPAD, wmma::mem_row_major);
    __syncthreads();

    #pragma unroll
    for (int it = 0; it < 16; ++it) {
        int r = wid + it * 8;
        int c = lane * 4;
        int gr = m0 + r, gc = n0 + c;
        if (gr < M) {
            float4 v = *reinterpret_cast<float4*>(Cs + r * CPAD + c);
            float4 bb = *reinterpret_cast<const float4*>(bias + gc);
            v.x += bb.x; v.y += bb.y; v.z += bb.z; v.w += bb.w;
            if (MODE == 1) {
                float4 rr = *reinterpret_cast<const float4*>(res + (size_t)gr * N + gc);
                float4 lv = *reinterpret_cast<const float4*>(ls + gc);
                v.x = rr.x + lv.x * v.x;
                v.y = rr.y + lv.y * v.y;
                v.z = rr.z + lv.z * v.z;
                v.w = rr.w + lv.w * v.w;
            } else if (MODE == 2) {
                v.x = gelu_exact(v.x);
                v.y = gelu_exact(v.y);
                v.z = gelu_exact(v.z);
                v.w = gelu_exact(v.w);
            }
            store4(C, (size_t)gr * N + gc, v);
        }
    }
}

// ---------------- wmma flash attention ----------------
// block: (qtile 64 rows, head, sample). 256 threads, 8 warps.
// smem: Ss[64][68] f32, Os[64][68] f32, Qs/Ks/Vs/Ps [64][72] bf16
#define SPAD 68
#define APAD2 72
#define SS_BYTES (64*SPAD*4)      /* 17408 */
#define QT_BYTES (64*APAD2*2)     /* 9216  */
#define ATTN_SMEM (2*SS_BYTES + 4*QT_BYTES)   /* 71680 */

__global__ __launch_bounds__(256, 1)
void attn_kernel(int tok_off, int n, const bf16* __restrict__ qkv, bf16* __restrict__ att) {
    extern __shared__ char smem[];
    float* Ss = reinterpret_cast<float*>(smem);
    float* Os = Ss + 64 * SPAD;
    bf16*  Qs = reinterpret_cast<bf16*>(smem + 2 * SS_BYTES);
    bf16*  Ks = Qs + 64 * APAD2;
    bf16*  Vs = Ks + 64 * APAD2;
    bf16*  Ps = Vs + 64 * APAD2;

    int b = blockIdx.z, h = blockIdx.y;
    int q0 = blockIdx.x * 64;
    int base = tok_off + b * n;
    int tid = threadIdx.x, wid = tid >> 5;
    int wr = wid >> 1, wc = wid & 1;   // warp: rows wr*16, cols wc*32

    // load + scale Q tile (clamped rows), init O
    const bf162 qscale = __halves2bfloat162(__float2bfloat16(0.125f), __float2bfloat16(0.125f));
    #pragma unroll
    for (int k = 0; k < 2; k++) {
        int i = tid + k * 256;                   // 512 chunks
        int row = i >> 3, c8 = i & 7;
        int qr = q0 + row; if (qr >= n) qr = n - 1;
        uint4 u = *reinterpret_cast<const uint4*>(qkv + (size_t)(base + qr) * QKVW + h * DH + c8 * 8);
        bf162* p = reinterpret_cast<bf162*>(&u);
        #pragma unroll
        for (int t = 0; t < 4; t++) p[t] = __hmul2(p[t], qscale);
        *reinterpret_cast<uint4*>(Qs + row * APAD2 + c8 * 8) = u;
    }
    for (int i = tid; i < 64 * SPAD; i += 256) Os[i] = 0.f;

    // per-row state (row = tid>>2, owned by 4-thread quad; all quad threads replicate)
    int rrow = tid >> 2;
    int quad = tid & 3;
    float mrow = -1e30f, lrow = 0.f;

    int nchunks = (n + 63) >> 6;
    for (int kc = 0; kc < nchunks; ++kc) {
        int kbase = kc * 64;
        int kcnt = min(64, n - kbase);
        __syncthreads();   // prior iter PV done before K/V overwrite
        #pragma unroll
        for (int k = 0; k < 2; k++) {
            int i = tid + k * 256;
            int row = i >> 3, c8 = i & 7;
            int kr = kbase + row; if (kr >= n) kr = n - 1;
            size_t o = (size_t)(base + kr) * QKVW + h * DH + c8 * 8;
            *reinterpret_cast<uint4*>(Ks + row * APAD2 + c8 * 8) =
                *reinterpret_cast<const uint4*>(qkv + DIM + o);
            *reinterpret_cast<uint4*>(Vs + row * APAD2 + c8 * 8) =
                *reinterpret_cast<const uint4*>(qkv + 2 * DIM + o);
        }
        __syncthreads();

        // S = Q K^T : each warp 16x32
        {
            wmma::fragment<wmma::accumulator, 16, 16, 16, float> sacc[2];
            #pragma unroll
            for (int j = 0; j < 2; j++) wmma::fill_fragment(sacc[j], 0.f);
            #pragma unroll
            for (int ks = 0; ks < 4; ++ks) {
                wmma::fragment<wmma::matrix_a, 16, 16, 16, bf16, wmma::row_major> af;
                wmma::load_matrix_sync(af, Qs + (wr * 16) * APAD2 + ks * 16, APAD2);
                #pragma unroll
                for (int j = 0; j < 2; j++) {
                    wmma::fragment<wmma::matrix_b, 16, 16, 16, bf16, wmma::col_major> bfm;
                    wmma::load_matrix_sync(bfm, Ks + (wc * 32 + j * 16) * APAD2 + ks * 16, APAD2);
                    wmma::mma_sync(sacc[j], af, bfm, sacc[j]);
                }
            }
            #pragma unroll
            for (int j = 0; j < 2; j++)
                wmma::store_matrix_sync(Ss + (wr * 16) * SPAD + wc * 32 + j * 16,
                                        sacc[j], SPAD, wmma::mem_row_major);
        }
        __syncthreads();

        // softmax: quad (4 threads) per row, 16 cols each
        {
            float sv[16];
            float* srow = Ss + rrow * SPAD + quad * 16;
            #pragma unroll
            for (int t = 0; t < 4; t++) {
                float4 f = *reinterpret_cast<float4*>(srow + t * 4);
                sv[t*4+0] = f.x; sv[t*4+1] = f.y; sv[t*4+2] = f.z; sv[t*4+3] = f.w;
            }
            float mx = -1e30f;
            #pragma unroll
            for (int t = 0; t < 16; t++) {
                int c = quad * 16 + t;
                if (c >= kcnt) sv[t] = -1e30f;
                mx = fmaxf(mx, sv[t]);
            }
            mx = fmaxf(mx, __shfl_xor_sync(0xffffffffu, mx, 1));
            mx = fmaxf(mx, __shfl_xor_sync(0xffffffffu, mx, 2));
            float mnew = fmaxf(mrow, mx);
            float corr = __expf(mrow - mnew);
            float psum = 0.f;
            bf16 pb[16];
            #pragma unroll
            for (int t = 0; t < 16; t++) {
                float p = __expf(sv[t] - mnew);   // exp(-huge)=0 for masked
                psum += p;
                pb[t] = __float2bfloat16(p);
            }
            psum += __shfl_xor_sync(0xffffffffu, psum, 1);
            psum += __shfl_xor_sync(0xffffffffu, psum, 2);
            lrow = lrow * corr + psum;
            mrow = mnew;
            // write P
            *reinterpret_cast<uint4*>(Ps + rrow * APAD2 + quad * 16)     = *reinterpret_cast<uint4*>(pb);
            *reinterpret_cast<uint4*>(Ps + rrow * APAD2 + quad * 16 + 8) = *reinterpret_cast<uint4*>(pb + 8);
            // rescale O row segment
            float* orow = Os + rrow * SPAD + quad * 16;
            #pragma unroll
            for (int t = 0; t < 4; t++) {
                float4 f = *reinterpret_cast<float4*>(orow + t * 4);
                f.x *= corr; f.y *= corr; f.z *= corr; f.w *= corr;
                *reinterpret_cast<float4*>(orow + t * 4) = f;
            }
        }
        __syncthreads();

        // O += P V : each warp 16x32
        {
            wmma::fragment<wmma::accumulator, 16, 16, 16, float> oacc[2];
            #pragma unroll
            for (int j = 0; j < 2; j++)
                wmma::load_matrix_sync(oacc[j], Os + (wr * 16) * SPAD + wc * 32 + j * 16,
                                       SPAD, wmma::mem_row_major);
            #pragma unroll
            for (int ks = 0; ks < 4; ++ks) {
                wmma::fragment<wmma::matrix_a, 16, 16, 16, bf16, wmma::row_major> af;
                wmma::load_matrix_sync(af, Ps + (wr * 16) * APAD2 + ks * 16, APAD2);
                #pragma unroll
                for (int j = 0; j < 2; j++) {
                    wmma::fragment<wmma::matrix_b, 16, 16, 16, bf16, wmma::row_major> bfm;
                    wmma::load_matrix_sync(bfm, Vs + (ks * 16) * APAD2 + wc * 32 + j * 16, APAD2);
                    wmma::mma_sync(oacc[j], af, bfm, oacc[j]);
                }
            }
            #pragma unroll
            for (int j = 0; j < 2; j++)
                wmma::store_matrix_sync(Os + (wr * 16) * SPAD + wc * 32 + j * 16,
                                        oacc[j], SPAD, wmma::mem_row_major);
        }
    }
    __syncthreads();

    // write O / l  (bf16)
    if (q0 + rrow < n) {
        float inv = 1.0f / lrow;
        float* orow = Os + rrow * SPAD + quad * 16;
        bf16 ob[16];
        #pragma unroll
        for (int t = 0; t < 16; t++) ob[t] = __float2bfloat16(orow[t] * inv);
        bf16* dst = att + (size_t)(base + q0 + rrow) * DIM + h * DH + quad * 16;
        *reinterpret_cast<uint4*>(dst)     = *reinterpret_cast<uint4*>(ob);
        *reinterpret_cast<uint4*>(dst + 8) = *reinterpret_cast<uint4*>(ob + 8);
    }
}

// ---------------- host launcher ----------------
extern "C" void kernel_launch(void* const* d_in, const int* in_sizes, int n_in,
                              void* d_out, int out_size) {
    const float* x0     = (const float*)d_in[0];
    const float* x1     = (const float*)d_in[1];
    const float* ln1_g  = (const float*)d_in[2];
    const float* ln1_b  = (const float*)d_in[3];
    const float* qkv_w  = (const float*)d_in[4];
    const float* qkv_b  = (const float*)d_in[5];
    const float* proj_w = (const float*)d_in[6];
    const float* proj_b = (const float*)d_in[7];
    const float* ls1    = (const float*)d_in[8];
    const float* ln2_g  = (const float*)d_in[9];
    const float* ln2_b  = (const float*)d_in[10];
    const float* fc1_w  = (const float*)d_in[11];
    const float* fc1_b  = (const float*)d_in[12];
    const float* fc2_w  = (const float*)d_in[13];
    const float* fc2_b  = (const float*)d_in[14];
    const float* ls2    = (const float*)d_in[15];
    float* out = (float*)d_out;

    float *px, *ph;
    bf16 *plnx, *pqkv, *patt, *pln2, *pfc1;
    bf16 *pqkvw, *pprojw, *pfc1w, *pfc2w;
    cudaGetSymbolAddress((void**)&px,    g_x);
    cudaGetSymbolAddress((void**)&ph,    g_h);
    cudaGetSymbolAddress((void**)&plnx,  g_lnx);
    cudaGetSymbolAddress((void**)&pqkv,  g_qkv);
    cudaGetSymbolAddress((void**)&patt,  g_att);
    cudaGetSymbolAddress((void**)&pln2,  g_ln2);
    cudaGetSymbolAddress((void**)&pfc1,  g_fc1);
    cudaGetSymbolAddress((void**)&pqkvw, g_qkvw);
    cudaGetSymbolAddress((void**)&pprojw,g_projw);
    cudaGetSymbolAddress((void**)&pfc1w, g_fc1w);
    cudaGetSymbolAddress((void**)&pfc2w, g_fc2w);

    cudaFuncSetAttribute(gemm_kernel<0,bf16>,  cudaFuncAttributeMaxDynamicSharedMemorySize, GEMM_SMEM);
    cudaFuncSetAttribute(gemm_kernel<1,float>, cudaFuncAttributeMaxDynamicSharedMemorySize, GEMM_SMEM);
    cudaFuncSetAttribute(gemm_kernel<2,bf16>,  cudaFuncAttributeMaxDynamicSharedMemorySize, GEMM_SMEM);
    cudaFuncSetAttribute(attn_kernel,          cudaFuncAttributeMaxDynamicSharedMemorySize, ATTN_SMEM);

    const int mtiles = (TTOT + BM - 1) / BM;  // 59

    // 1. pack x + convert weights
    pack_x<<<(TTOT * DIM / 4 + 255) / 256, 256>>>(x0, x1);
    cvt_kernel<<<(DIM*QKVW/4 + 255)/256, 256>>>(qkv_w,  pqkvw,  DIM*QKVW/4);
    cvt_kernel<<<(DIM*DIM/4  + 255)/256, 256>>>(proj_w, pprojw, DIM*DIM/4);
    cvt_kernel<<<(DIM*HID/4  + 255)/256, 256>>>(fc1_w,  pfc1w,  DIM*HID/4);
    cvt_kernel<<<(HID*DIM/4  + 255)/256, 256>>>(fc2_w,  pfc2w,  HID*DIM/4);
    // 2. LN1 -> bf16
    ln_kernel<<<TTOT, 256>>>(px, ln1_g, ln1_b, plnx);
    // 3. QKV gemm (bf16 out)
    gemm_kernel<0,bf16><<<dim3(mtiles, QKVW / BN), 256, GEMM_SMEM>>>(
        plnx, pqkvw, qkv_b, nullptr, nullptr, pqkv, TTOT, QKVW, DIM);
    // 4. attention
    attn_kernel<<<dim3((T0N + 63) / 64, NH, T0B), 256, ATTN_SMEM>>>(0, T0N, pqkv, patt);
    attn_kernel<<<dim3((T1N + 63) / 64, NH, T1B), 256, ATTN_SMEM>>>(T0B * T0N, T1N, pqkv, patt);
    // 5. proj + residual -> h (fp32)
    gemm_kernel<1,float><<<dim3(mtiles, DIM / BN), 256, GEMM_SMEM>>>(
        patt, pprojw, proj_b, px, ls1, ph, TTOT, DIM, DIM);
    // 6. LN2 -> bf16
    ln_kernel<<<TTOT, 256>>>(ph, ln2_g, ln2_b, pln2);
    // 7. fc1 + gelu (bf16 out)
    gemm_kernel<2,bf16><<<dim3(mtiles, HID / BN), 256, GEMM_SMEM>>>(
        pln2, pfc1w, fc1_b, nullptr, nullptr, pfc1, TTOT, HID, DIM);
    // 8. fc2 + residual -> out (fp32)
    gemm_kernel<1,float><<<dim3(mtiles, DIM / BN), 256, GEMM_SMEM>>>(
        pfc1, pfc2w, fc2_b, ph, ls2, out, TTOT, DIM, HID);
}

// round 4
// speedup vs baseline: 3.2531x; 1.1753x over previous
#include <cuda_runtime.h>
#include <cuda_bf16.h>
#include <mma.h>
#include <math.h>

using namespace nvcuda;

#define T0B 4
#define T0N 1370
#define T1B 8
#define T1N 257
#define TTOT (T0B*T0N + T1B*T1N)   /* 7536 */
#define DIM 1024
#define NH 16
#define DH 64
#define HID 4096
#define QKVW (3*DIM)

typedef __nv_bfloat16 bf16;
typedef __nv_bfloat162 bf162;

// ---------------- scratch (static device globals; no allocation) ----------------
__device__ float g_x[TTOT*DIM];                    // packed input (residual 1)
__device__ float g_h[TTOT*DIM];                    // residual 2
__device__ bf16  g_lnx[TTOT*DIM];
__device__ bf16  g_qkv[(size_t)TTOT*QKVW];
__device__ bf16  g_att[TTOT*DIM];
__device__ bf16  g_ln2[TTOT*DIM];
__device__ bf16  g_fc1[(size_t)TTOT*HID];
__device__ bf16  g_qkvw[DIM*QKVW];
__device__ bf16  g_projw[DIM*DIM];
__device__ bf16  g_fc1w[DIM*HID];
__device__ bf16  g_fc2w[HID*DIM];

// ---------------- helpers ----------------
__device__ __forceinline__ float gelu_exact(float x) {
    return 0.5f * x * (1.0f + erff(x * 0.70710678118654752f));
}
__device__ __forceinline__ unsigned smem_u32(const void* p) {
    return (unsigned)__cvta_generic_to_shared(p);
}
#define CP_ASYNC16(dst, src) \
    asm volatile("cp.async.cg.shared.global [%0], [%1], 16;\n" :: "r"(dst), "l"(src))
#define CP_COMMIT() asm volatile("cp.async.commit_group;\n" ::: "memory")
#define CP_WAIT(N)  asm volatile("cp.async.wait_group %0;\n" :: "n"(N) : "memory")

__device__ __forceinline__ void store4(float* C, size_t idx, float4 v) {
    *reinterpret_cast<float4*>(C + idx) = v;
}
__device__ __forceinline__ void store4(bf16* C, size_t idx, float4 v) {
    bf162 lo = __halves2bfloat162(__float2bfloat16(v.x), __float2bfloat16(v.y));
    bf162 hi = __halves2bfloat162(__float2bfloat16(v.z), __float2bfloat16(v.w));
    uint2 u;
    u.x = *reinterpret_cast<unsigned*>(&lo);
    u.y = *reinterpret_cast<unsigned*>(&hi);
    *reinterpret_cast<uint2*>(C + idx) = u;
}

// ---------------- pack x0,x1 -> g_x ----------------
__global__ void pack_x(const float* __restrict__ x0, const float* __restrict__ x1) {
    size_t i = (size_t)blockIdx.x * 256 + threadIdx.x;
    size_t n4 = (size_t)TTOT * DIM / 4;
    if (i >= n4) return;
    size_t e = i * 4;
    size_t split = (size_t)T0B * T0N * DIM;
    float4 v = (e < split) ? reinterpret_cast<const float4*>(x0)[i]
                           : reinterpret_cast<const float4*>(x1)[(e - split) >> 2];
    reinterpret_cast<float4*>(g_x)[i] = v;
}

// ---------------- f32 -> bf16 weight convert ----------------
__global__ void cvt_kernel(const float* __restrict__ in, bf16* __restrict__ out, int n4) {
    int i = blockIdx.x * 256 + threadIdx.x;
    if (i >= n4) return;
    float4 v = reinterpret_cast<const float4*>(in)[i];
    store4(out, (size_t)i * 4, v);
}

// ---------------- layernorm: fp32 in -> bf16 out ----------------
__global__ void ln_kernel(const float* __restrict__ in, const float* __restrict__ gw,
                          const float* __restrict__ bw, bf16* __restrict__ out) {
    int row = blockIdx.x;
    int tid = threadIdx.x;
    const float4 v = reinterpret_cast<const float4*>(in + (size_t)row * DIM)[tid];
    float s  = v.x + v.y + v.z + v.w;
    float s2 = v.x*v.x + v.y*v.y + v.z*v.z + v.w*v.w;
    #pragma unroll
    for (int o = 16; o; o >>= 1) {
        s  += __shfl_down_sync(0xffffffffu, s,  o);
        s2 += __shfl_down_sync(0xffffffffu, s2, o);
    }
    __shared__ float ss[8], ss2[8];
    __shared__ float mb, rb;
    int w = tid >> 5, l = tid & 31;
    if (l == 0) { ss[w] = s; ss2[w] = s2; }
    __syncthreads();
    if (tid == 0) {
        float a = 0.f, a2 = 0.f;
        #pragma unroll
        for (int i = 0; i < 8; i++) { a += ss[i]; a2 += ss2[i]; }
        float m = a * (1.0f / DIM);
        float var = a2 * (1.0f / DIM) - m * m;
        mb = m;
        rb = rsqrtf(var + 1e-5f);
    }
    __syncthreads();
    float m = mb, r = rb;
    float4 g4 = reinterpret_cast<const float4*>(gw)[tid];
    float4 b4 = reinterpret_cast<const float4*>(bw)[tid];
    float4 o;
    o.x = (v.x - m) * r * g4.x + b4.x;
    o.y = (v.y - m) * r * g4.y + b4.y;
    o.z = (v.z - m) * r * g4.z + b4.z;
    o.w = (v.w - m) * r * g4.w + b4.w;
    store4(out, (size_t)row * DIM + tid * 4, o);
}

// ---------------- bf16 wmma GEMM, cp.async double-buffered, 2 CTAs/SM ----------------
// MODE 0: C = AB + bias         MODE 1: C = res + ls*(AB+bias)    MODE 2: C = gelu(AB+bias)
#define BM 128
#define BN 128
#define BK 64
#define ASTR 72
#define BSTR 136
#define A_BYTES (BM*ASTR*2)    /* 18432 */
#define B_BYTES (BK*BSTR*2)    /* 17408 */
#define STAGE_BYTES (A_BYTES + B_BYTES)   /* 35840 */
#define CPAD 132
#define GEMM_SMEM (2*STAGE_BYTES)  /* 71680 > Cs(128*132*4=67584); 2 CTAs = 143KB < 228KB */

template<int MODE, typename OT>
__global__ __launch_bounds__(256, 2)
void gemm_kernel(const bf16* __restrict__ A, const bf16* __restrict__ B,
                 const float* __restrict__ bias, const float* __restrict__ res,
                 const float* __restrict__ ls, OT* __restrict__ C,
                 int M, int N, int K) {
    extern __shared__ char smem[];
    int tid = threadIdx.x;
    int wid = tid >> 5, lane = tid & 31;
    int m0 = blockIdx.x * BM, n0 = blockIdx.y * BN;
    int wr = wid >> 2, wc = wid & 3;   // warp tile (wr*64 rows, wc*32 cols)

    wmma::fragment<wmma::accumulator, 16, 16, 16, float> acc[4][2];
    #pragma unroll
    for (int i = 0; i < 4; i++)
        #pragma unroll
        for (int j = 0; j < 2; j++)
            wmma::fill_fragment(acc[i][j], 0.0f);

    int nk = K / BK;

    auto load_stage = [&](int kt) {
        char* As = smem + (kt & 1) * STAGE_BYTES;
        char* Bs = As + A_BYTES;
        // A tile: 128 rows x 64 cols -> 1024 16B chunks, 4/thread
        #pragma unroll
        for (int k = 0; k < 4; k++) {
            int i = tid + k * 256;
            int row = i >> 3, c8 = i & 7;
            int grow = m0 + row; if (grow >= M) grow = M - 1;
            const bf16* src = A + (size_t)grow * K + kt * BK + c8 * 8;
            unsigned dst = smem_u32(As + row * (ASTR * 2) + c8 * 16);
            CP_ASYNC16(dst, src);
        }
        // B tile: 64 rows x 128 cols -> 1024 16B chunks, 4/thread
        #pragma unroll
        for (int k = 0; k < 4; k++) {
            int i = tid + k * 256;
            int row = i >> 4, c8 = i & 15;
            const bf16* src = B + (size_t)(kt * BK + row) * N + n0 + c8 * 8;
            unsigned dst = smem_u32(Bs + row * (BSTR * 2) + c8 * 16);
            CP_ASYNC16(dst, src);
        }
        CP_COMMIT();
    };

    load_stage(0);

    for (int kt = 0; kt < nk; ++kt) {
        if (kt + 1 < nk) { load_stage(kt + 1); CP_WAIT(1); }
        else             { CP_WAIT(0); }
        __syncthreads();

        bf16* As = reinterpret_cast<bf16*>(smem + (kt & 1) * STAGE_BYTES);
        bf16* Bs = reinterpret_cast<bf16*>(smem + (kt & 1) * STAGE_BYTES + A_BYTES);

        #pragma unroll
        for (int ks = 0; ks < 4; ++ks) {
            wmma::fragment<wmma::matrix_a, 16, 16, 16, bf16, wmma::row_major> af[4];
            wmma::fragment<wmma::matrix_b, 16, 16, 16, bf16, wmma::row_major> bfm[2];
            #pragma unroll
            for (int i = 0; i < 4; i++)
                wmma::load_matrix_sync(af[i], As + (wr * 64 + i * 16) * ASTR + ks * 16, ASTR);
            #pragma unroll
            for (int j = 0; j < 2; j++)
                wmma::load_matrix_sync(bfm[j], Bs + (ks * 16) * BSTR + wc * 32 + j * 16, BSTR);
            #pragma unroll
            for (int i = 0; i < 4; i++)
                #pragma unroll
                for (int j = 0; j < 2; j++)
                    wmma::mma_sync(acc[i][j], af[i], bfm[j], acc[i][j]);
        }
        __syncthreads();
    }

    // epilogue via smem
    float* Cs = reinterpret_cast<float*>(smem);
    #pragma unroll
    for (int i = 0; i < 4; i++)
        #pragma unroll
        for (int j = 0; j < 2; j++)
            wmma::store_matrix_sync(Cs + (wr * 64 + i * 16) * CPAD + wc * 32 + j * 16,
                                    acc[i][j], CPAD, wmma::mem_row_major);
    __syncthreads();

    #pragma unroll
    for (int it = 0; it < 16; ++it) {
        int r = wid + it * 8;
        int c = lane * 4;
        int gr = m0 + r, gc = n0 + c;
        if (gr < M) {
            float4 v = *reinterpret_cast<float4*>(Cs + r * CPAD + c);
            float4 bb = *reinterpret_cast<const float4*>(bias + gc);
            v.x += bb.x; v.y += bb.y; v.z += bb.z; v.w += bb.w;
            if (MODE == 1) {
                float4 rr = *reinterpret_cast<const float4*>(res + (size_t)gr * N + gc);
                float4 lv = *reinterpret_cast<const float4*>(ls + gc);
                v.x = rr.x + lv.x * v.x;
                v.y = rr.y + lv.y * v.y;
                v.z = rr.z + lv.z * v.z;
                v.w = rr.w + lv.w * v.w;
            } else if (MODE == 2) {
                v.x = gelu_exact(v.x);
                v.y = gelu_exact(v.y);
                v.z = gelu_exact(v.z);
                v.w = gelu_exact(v.w);
            }
            store4(C, (size_t)gr * N + gc, v);
        }
    }
}

// ---------------- wmma flash attention, 2 CTAs/SM ----------------
#define SPAD 68
#define APAD2 72
#define SS_BYTES (64*SPAD*4)      /* 17408 */
#define QT_BYTES (64*APAD2*2)     /* 9216  */
#define ATTN_SMEM (2*SS_BYTES + 4*QT_BYTES)   /* 71680; 2 CTAs = 143KB */

__global__ __launch_bounds__(256, 2)
void attn_kernel(int tok_off, int n, const bf16* __restrict__ qkv, bf16* __restrict__ att) {
    extern __shared__ char smem[];
    float* Ss = reinterpret_cast<float*>(smem);
    float* Os = Ss + 64 * SPAD;
    bf16*  Qs = reinterpret_cast<bf16*>(smem + 2 * SS_BYTES);
    bf16*  Ks = Qs + 64 * APAD2;
    bf16*  Vs = Ks + 64 * APAD2;
    bf16*  Ps = Vs + 64 * APAD2;

    int b = blockIdx.z, h = blockIdx.y;
    int q0 = blockIdx.x * 64;
    int base = tok_off + b * n;
    int tid = threadIdx.x, wid = tid >> 5;
    int wr = wid >> 1, wc = wid & 1;

    const bf162 qscale = __halves2bfloat162(__float2bfloat16(0.125f), __float2bfloat16(0.125f));
    #pragma unroll
    for (int k = 0; k < 2; k++) {
        int i = tid + k * 256;
        int row = i >> 3, c8 = i & 7;
        int qr = q0 + row; if (qr >= n) qr = n - 1;
        uint4 u = *reinterpret_cast<const uint4*>(qkv + (size_t)(base + qr) * QKVW + h * DH + c8 * 8);
        bf162* p = reinterpret_cast<bf162*>(&u);
        #pragma unroll
        for (int t = 0; t < 4; t++) p[t] = __hmul2(p[t], qscale);
        *reinterpret_cast<uint4*>(Qs + row * APAD2 + c8 * 8) = u;
    }
    for (int i = tid; i < 64 * SPAD; i += 256) Os[i] = 0.f;

    int rrow = tid >> 2;
    int quad = tid & 3;
    float mrow = -1e30f, lrow = 0.f;

    int nchunks = (n + 63) >> 6;
    for (int kc = 0; kc < nchunks; ++kc) {
        int kbase = kc * 64;
        int kcnt = min(64, n - kbase);
        __syncthreads();
        #pragma unroll
        for (int k = 0; k < 2; k++) {
            int i = tid + k * 256;
            int row = i >> 3, c8 = i & 7;
            int kr = kbase + row; if (kr >= n) kr = n - 1;
            size_t o = (size_t)(base + kr) * QKVW + h * DH + c8 * 8;
            *reinterpret_cast<uint4*>(Ks + row * APAD2 + c8 * 8) =
                *reinterpret_cast<const uint4*>(qkv + DIM + o);
            *reinterpret_cast<uint4*>(Vs + row * APAD2 + c8 * 8) =
                *reinterpret_cast<const uint4*>(qkv + 2 * DIM + o);
        }
        __syncthreads();

        {
            wmma::fragment<wmma::accumulator, 16, 16, 16, float> sacc[2];
            #pragma unroll
            for (int j = 0; j < 2; j++) wmma::fill_fragment(sacc[j], 0.f);
            #pragma unroll
            for (int ks = 0; ks < 4; ++ks) {
                wmma::fragment<wmma::matrix_a, 16, 16, 16, bf16, wmma::row_major> af;
                wmma::load_matrix_sync(af, Qs + (wr * 16) * APAD2 + ks * 16, APAD2);
                #pragma unroll
                for (int j = 0; j < 2; j++) {
                    wmma::fragment<wmma::matrix_b, 16, 16, 16, bf16, wmma::col_major> bfm;
                    wmma::load_matrix_sync(bfm, Ks + (wc * 32 + j * 16) * APAD2 + ks * 16, APAD2);
                    wmma::mma_sync(sacc[j], af, bfm, sacc[j]);
                }
            }
            #pragma unroll
            for (int j = 0; j < 2; j++)
                wmma::store_matrix_sync(Ss + (wr * 16) * SPAD + wc * 32 + j * 16,
                                        sacc[j], SPAD, wmma::mem_row_major);
        }
        __syncthreads();

        {
            float sv[16];
            float* srow = Ss + rrow * SPAD + quad * 16;
            #pragma unroll
            for (int t = 0; t < 4; t++) {
                float4 f = *reinterpret_cast<float4*>(srow + t * 4);
                sv[t*4+0] = f.x; sv[t*4+1] = f.y; sv[t*4+2] = f.z; sv[t*4+3] = f.w;
            }
            float mx = -1e30f;
            #pragma unroll
            for (int t = 0; t < 16; t++) {
                int c = quad * 16 + t;
                if (c >= kcnt) sv[t] = -1e30f;
                mx = fmaxf(mx, sv[t]);
            }
            mx = fmaxf(mx, __shfl_xor_sync(0xffffffffu, mx, 1));
            mx = fmaxf(mx, __shfl_xor_sync(0xffffffffu, mx, 2));
            float mnew = fmaxf(mrow, mx);
            float corr = __expf(mrow - mnew);
            float psum = 0.f;
            bf16 pb[16];
            #pragma unroll
            for (int t = 0; t < 16; t++) {
                float p = __expf(sv[t] - mnew);
                psum += p;
                pb[t] = __float2bfloat16(p);
            }
            psum += __shfl_xor_sync(0xffffffffu, psum, 1);
            psum += __shfl_xor_sync(0xffffffffu, psum, 2);
            lrow = lrow * corr + psum;
            mrow = mnew;
            *reinterpret_cast<uint4*>(Ps + rrow * APAD2 + quad * 16)     = *reinterpret_cast<uint4*>(pb);
            *reinterpret_cast<uint4*>(Ps + rrow * APAD2 + quad * 16 + 8) = *reinterpret_cast<uint4*>(pb + 8);
            float* orow = Os + rrow * SPAD + quad * 16;
            #pragma unroll
            for (int t = 0; t < 4; t++) {
                float4 f = *reinterpret_cast<float4*>(orow + t * 4);
                f.x *= corr; f.y *= corr; f.z *= corr; f.w *= corr;
                *reinterpret_cast<float4*>(orow + t * 4) = f;
            }
        }
        __syncthreads();

        {
            wmma::fragment<wmma::accumulator, 16, 16, 16, float> oacc[2];
            #pragma unroll
            for (int j = 0; j < 2; j++)
                wmma::load_matrix_sync(oacc[j], Os + (wr * 16) * SPAD + wc * 32 + j * 16,
                                       SPAD, wmma::mem_row_major);
            #pragma unroll
            for (int ks = 0; ks < 4; ++ks) {
                wmma::fragment<wmma::matrix_a, 16, 16, 16, bf16, wmma::row_major> af;
                wmma::load_matrix_sync(af, Ps + (wr * 16) * APAD2 + ks * 16, APAD2);
                #pragma unroll
                for (int j = 0; j < 2; j++) {
                    wmma::fragment<wmma::matrix_b, 16, 16, 16, bf16, wmma::row_major> bfm;
                    wmma::load_matrix_sync(bfm, Vs + (ks * 16) * APAD2 + wc * 32 + j * 16, APAD2);
                    wmma::mma_sync(oacc[j], af, bfm, oacc[j]);
                }
            }
            #pragma unroll
            for (int j = 0; j < 2; j++)
                wmma::store_matrix_sync(Os + (wr * 16) * SPAD + wc * 32 + j * 16,
                                        oacc[j], SPAD, wmma::mem_row_major);
        }
    }
    __syncthreads();

    if (q0 + rrow < n) {
        float inv = 1.0f / lrow;
        float* orow = Os + rrow * SPAD + quad * 16;
        bf16 ob[16];
        #pragma unroll
        for (int t = 0; t < 16; t++) ob[t] = __float2bfloat16(orow[t] * inv);
        bf16* dst = att + (size_t)(base + q0 + rrow) * DIM + h * DH + quad * 16;
        *reinterpret_cast<uint4*>(dst)     = *reinterpret_cast<uint4*>(ob);
        *reinterpret_cast<uint4*>(dst + 8) = *reinterpret_cast<uint4*>(ob + 8);
    }
}

// ---------------- host launcher ----------------
extern "C" void kernel_launch(void* const* d_in, const int* in_sizes, int n_in,
                              void* d_out, int out_size) {
    const float* x0     = (const float*)d_in[0];
    const float* x1     = (const float*)d_in[1];
    const float* ln1_g  = (const float*)d_in[2];
    const float* ln1_b  = (const float*)d_in[3];
    const float* qkv_w  = (const float*)d_in[4];
    const float* qkv_b  = (const float*)d_in[5];
    const float* proj_w = (const float*)d_in[6];
    const float* proj_b = (const float*)d_in[7];
    const float* ls1    = (const float*)d_in[8];
    const float* ln2_g  = (const float*)d_in[9];
    const float* ln2_b  = (const float*)d_in[10];
    const float* fc1_w  = (const float*)d_in[11];
    const float* fc1_b  = (const float*)d_in[12];
    const float* fc2_w  = (const float*)d_in[13];
    const float* fc2_b  = (const float*)d_in[14];
    const float* ls2    = (const float*)d_in[15];
    float* out = (float*)d_out;

    float *px, *ph;
    bf16 *plnx, *pqkv, *patt, *pln2, *pfc1;
    bf16 *pqkvw, *pprojw, *pfc1w, *pfc2w;
    cudaGetSymbolAddress((void**)&px,    g_x);
    cudaGetSymbolAddress((void**)&ph,    g_h);
    cudaGetSymbolAddress((void**)&plnx,  g_lnx);
    cudaGetSymbolAddress((void**)&pqkv,  g_qkv);
    cudaGetSymbolAddress((void**)&patt,  g_att);
    cudaGetSymbolAddress((void**)&pln2,  g_ln2);
    cudaGetSymbolAddress((void**)&pfc1,  g_fc1);
    cudaGetSymbolAddress((void**)&pqkvw, g_qkvw);
    cudaGetSymbolAddress((void**)&pprojw,g_projw);
    cudaGetSymbolAddress((void**)&pfc1w, g_fc1w);
    cudaGetSymbolAddress((void**)&pfc2w, g_fc2w);

    cudaFuncSetAttribute(gemm_kernel<0,bf16>,  cudaFuncAttributeMaxDynamicSharedMemorySize, GEMM_SMEM);
    cudaFuncSetAttribute(gemm_kernel<1,float>, cudaFuncAttributeMaxDynamicSharedMemorySize, GEMM_SMEM);
    cudaFuncSetAttribute(gemm_kernel<2,bf16>,  cudaFuncAttributeMaxDynamicSharedMemorySize, GEMM_SMEM);
    cudaFuncSetAttribute(attn_kernel,          cudaFuncAttributeMaxDynamicSharedMemorySize, ATTN_SMEM);

    const int mtiles = (TTOT + BM - 1) / BM;  // 59

    // 1. pack x + convert weights
    pack_x<<<(TTOT * DIM / 4 + 255) / 256, 256>>>(x0, x1);
    cvt_kernel<<<(DIM*QKVW/4 + 255)/256, 256>>>(qkv_w,  pqkvw,  DIM*QKVW/4);
    cvt_kernel<<<(DIM*DIM/4  + 255)/256, 256>>>(proj_w, pprojw, DIM*DIM/4);
    cvt_kernel<<<(DIM*HID/4  + 255)/256, 256>>>(fc1_w,  pfc1w,  DIM*HID/4);
    cvt_kernel<<<(HID*DIM/4  + 255)/256, 256>>>(fc2_w,  pfc2w,  HID*DIM/4);
    // 2. LN1 -> bf16
    ln_kernel<<<TTOT, 256>>>(px, ln1_g, ln1_b, plnx);
    // 3. QKV gemm (bf16 out)
    gemm_kernel<0,bf16><<<dim3(mtiles, QKVW / BN), 256, GEMM_SMEM>>>(
        plnx, pqkvw, qkv_b, nullptr, nullptr, pqkv, TTOT, QKVW, DIM);
    // 4. attention
    attn_kernel<<<dim3((T0N + 63) / 64, NH, T0B), 256, ATTN_SMEM>>>(0, T0N, pqkv, patt);
    attn_kernel<<<dim3((T1N + 63) / 64, NH, T1B), 256, ATTN_SMEM>>>(T0B * T0N, T1N, pqkv, patt);
    // 5. proj + residual -> h (fp32)
    gemm_kernel<1,float><<<dim3(mtiles, DIM / BN), 256, GEMM_SMEM>>>(
        patt, pprojw, proj_b, px, ls1, ph, TTOT, DIM, DIM);
    // 6. LN2 -> bf16
    ln_kernel<<<TTOT, 256>>>(ph, ln2_g, ln2_b, pln2);
    // 7. fc1 + gelu (bf16 out)
    gemm_kernel<2,bf16><<<dim3(mtiles, HID / BN), 256, GEMM_SMEM>>>(
        pln2, pfc1w, fc1_b, nullptr, nullptr, pfc1, TTOT, HID, DIM);
    // 8. fc2 + residual -> out (fp32)
    gemm_kernel<1,float><<<dim3(mtiles, DIM / BN), 256, GEMM_SMEM>>>(
        pfc1, pfc2w, fc2_b, ph, ls2, out, TTOT, DIM, HID);
}

// round 5
// speedup vs baseline: 3.3652x; 1.0345x over previous
#include <cuda_runtime.h>
#include <cuda_bf16.h>
#include <mma.h>
#include <math.h>

using namespace nvcuda;

#define T0B 4
#define T0N 1370
#define T1B 8
#define T1N 257
#define TTOT (T0B*T0N + T1B*T1N)   /* 7536 */
#define DIM 1024
#define NH 16
#define DH 64
#define HID 4096
#define QKVW (3*DIM)

typedef __nv_bfloat16 bf16;
typedef __nv_bfloat162 bf162;

// ---------------- scratch (static device globals; no allocation) ----------------
__device__ float g_x[TTOT*DIM];                    // packed input (residual 1)
__device__ float g_h[TTOT*DIM];                    // residual 2
__device__ bf16  g_lnx[TTOT*DIM];
__device__ bf16  g_qkv[(size_t)TTOT*QKVW];
__device__ bf16  g_att[TTOT*DIM];
__device__ bf16  g_ln2[TTOT*DIM];
__device__ bf16  g_fc1[(size_t)TTOT*HID];
__device__ bf16  g_qkvw[DIM*QKVW];
__device__ bf16  g_projw[DIM*DIM];
__device__ bf16  g_fc1w[DIM*HID];
__device__ bf16  g_fc2w[HID*DIM];

// ---------------- helpers ----------------
__device__ __forceinline__ float gelu_exact(float x) {
    return 0.5f * x * (1.0f + erff(x * 0.70710678118654752f));
}
__device__ __forceinline__ unsigned smem_u32(const void* p) {
    return (unsigned)__cvta_generic_to_shared(p);
}
#define CP_ASYNC16(dst, src) \
    asm volatile("cp.async.cg.shared.global [%0], [%1], 16;\n" :: "r"(dst), "l"(src))
#define CP_COMMIT() asm volatile("cp.async.commit_group;\n" ::: "memory")
#define CP_WAIT(N)  asm volatile("cp.async.wait_group %0;\n" :: "n"(N) : "memory")

__device__ __forceinline__ void store4(float* C, size_t idx, float4 v) {
    *reinterpret_cast<float4*>(C + idx) = v;
}
__device__ __forceinline__ void store4(bf16* C, size_t idx, float4 v) {
    bf162 lo = __halves2bfloat162(__float2bfloat16(v.x), __float2bfloat16(v.y));
    bf162 hi = __halves2bfloat162(__float2bfloat16(v.z), __float2bfloat16(v.w));
    uint2 u;
    u.x = *reinterpret_cast<unsigned*>(&lo);
    u.y = *reinterpret_cast<unsigned*>(&hi);
    *reinterpret_cast<uint2*>(C + idx) = u;
}

// ---------------- all-weights f32 -> bf16 convert (one launch) ----------------
#define CVT_S0 (DIM*QKVW/4)
#define CVT_S1 (CVT_S0 + DIM*DIM/4)
#define CVT_S2 (CVT_S1 + DIM*HID/4)
#define CVT_S3 (CVT_S2 + HID*DIM/4)
__global__ void cvt_all_kernel(const float* __restrict__ w0, const float* __restrict__ w1,
                               const float* __restrict__ w2, const float* __restrict__ w3) {
    int i = blockIdx.x * 256 + threadIdx.x;
    if (i >= CVT_S3) return;
    const float* src; bf16* dst; int off;
    if (i < CVT_S0)      { src = w0; dst = g_qkvw;  off = i; }
    else if (i < CVT_S1) { src = w1; dst = g_projw; off = i - CVT_S0; }
    else if (i < CVT_S2) { src = w2; dst = g_fc1w;  off = i - CVT_S1; }
    else                 { src = w3; dst = g_fc2w;  off = i - CVT_S2; }
    float4 v = reinterpret_cast<const float4*>(src)[off];
    store4(dst, (size_t)off * 4, v);
}

// ---------------- LN1 fused with pack: x0/x1 -> g_x (f32) + g_lnx (bf16) ----------------
// PACK=1: read from ragged x0/x1, also write packed fp32 to xout.
template<int PACK>
__global__ void ln_kernel(const float* __restrict__ in0, const float* __restrict__ in1,
                          const float* __restrict__ gw, const float* __restrict__ bw,
                          float* __restrict__ xout, bf16* __restrict__ out) {
    int row = blockIdx.x;
    int tid = threadIdx.x;
    const float* src;
    if (PACK) {
        const int split = T0B * T0N;
        src = (row < split) ? in0 + (size_t)row * DIM
                            : in1 + (size_t)(row - split) * DIM;
    } else {
        src = in0 + (size_t)row * DIM;
    }
    const float4 v = reinterpret_cast<const float4*>(src)[tid];
    if (PACK)
        reinterpret_cast<float4*>(xout + (size_t)row * DIM)[tid] = v;
    float s  = v.x + v.y + v.z + v.w;
    float s2 = v.x*v.x + v.y*v.y + v.z*v.z + v.w*v.w;
    #pragma unroll
    for (int o = 16; o; o >>= 1) {
        s  += __shfl_down_sync(0xffffffffu, s,  o);
        s2 += __shfl_down_sync(0xffffffffu, s2, o);
    }
    __shared__ float ss[8], ss2[8];
    __shared__ float mb, rb;
    int w = tid >> 5, l = tid & 31;
    if (l == 0) { ss[w] = s; ss2[w] = s2; }
    __syncthreads();
    if (tid == 0) {
        float a = 0.f, a2 = 0.f;
        #pragma unroll
        for (int i = 0; i < 8; i++) { a += ss[i]; a2 += ss2[i]; }
        float m = a * (1.0f / DIM);
        float var = a2 * (1.0f / DIM) - m * m;
        mb = m;
        rb = rsqrtf(var + 1e-5f);
    }
    __syncthreads();
    float m = mb, r = rb;
    float4 g4 = reinterpret_cast<const float4*>(gw)[tid];
    float4 b4 = reinterpret_cast<const float4*>(bw)[tid];
    float4 o;
    o.x = (v.x - m) * r * g4.x + b4.x;
    o.y = (v.y - m) * r * g4.y + b4.y;
    o.z = (v.z - m) * r * g4.z + b4.z;
    o.w = (v.w - m) * r * g4.w + b4.w;
    store4(out, (size_t)row * DIM + tid * 4, o);
}

// ---------------- bf16 wmma GEMM, 3-stage cp.async, single sync/iter, 2 CTAs/SM ----------------
// MODE 0: C = AB + bias   MODE 1: C = res + ls*(AB+bias)   MODE 2: C = gelu(AB+bias)
#define BM 128
#define BN 128
#define BK 64
#define ASTR 72
#define BSTR 136
#define A_BYTES (BM*ASTR*2)    /* 18432 */
#define B_BYTES (BK*BSTR*2)    /* 17408 */
#define STAGE_BYTES (A_BYTES + B_BYTES)   /* 35840 */
#define NST 3
#define CPAD 132
#define GEMM_SMEM (NST*STAGE_BYTES)  /* 107520 > Cs(67584); x2 CTAs = 215KB < 228KB */

template<int MODE, typename OT>
__global__ __launch_bounds__(256, 2)
void gemm_kernel(const bf16* __restrict__ A, const bf16* __restrict__ B,
                 const float* __restrict__ bias, const float* __restrict__ res,
                 const float* __restrict__ ls, OT* __restrict__ C,
                 int M, int N, int K) {
    extern __shared__ char smem[];
    int tid = threadIdx.x;
    int wid = tid >> 5, lane = tid & 31;
    int m0 = blockIdx.x * BM, n0 = blockIdx.y * BN;
    int wr = wid >> 2, wc = wid & 3;   // warp tile (wr*64 rows, wc*32 cols)

    wmma::fragment<wmma::accumulator, 16, 16, 16, float> acc[4][2];
    #pragma unroll
    for (int i = 0; i < 4; i++)
        #pragma unroll
        for (int j = 0; j < 2; j++)
            wmma::fill_fragment(acc[i][j], 0.0f);

    int nk = K / BK;

    auto load_stage = [&](int kt, int slot) {
        char* As = smem + slot * STAGE_BYTES;
        char* Bs = As + A_BYTES;
        #pragma unroll
        for (int k = 0; k < 4; k++) {
            int i = tid + k * 256;
            int row = i >> 3, c8 = i & 7;
            int grow = m0 + row; if (grow >= M) grow = M - 1;
            const bf16* src = A + (size_t)grow * K + kt * BK + c8 * 8;
            unsigned dst = smem_u32(As + row * (ASTR * 2) + c8 * 16);
            CP_ASYNC16(dst, src);
        }
        #pragma unroll
        for (int k = 0; k < 4; k++) {
            int i = tid + k * 256;
            int row = i >> 4, c8 = i & 15;
            const bf16* src = B + (size_t)(kt * BK + row) * N + n0 + c8 * 8;
            unsigned dst = smem_u32(Bs + row * (BSTR * 2) + c8 * 16);
            CP_ASYNC16(dst, src);
        }
    };

    // prologue: 2 stages in flight
    load_stage(0, 0); CP_COMMIT();
    if (nk > 1) { load_stage(1, 1); CP_COMMIT(); } else { CP_COMMIT(); }

    int slot = 0, lslot = 2 % NST;
    for (int kt = 0; kt < nk; ++kt) {
        CP_WAIT(1);
        __syncthreads();
        // issue next load into buffer (kt+2)%3 (consumed at kt-1, protected by sync above)
        if (kt + 2 < nk) load_stage(kt + 2, lslot);
        CP_COMMIT();

        bf16* As = reinterpret_cast<bf16*>(smem + slot * STAGE_BYTES);
        bf16* Bs = reinterpret_cast<bf16*>(smem + slot * STAGE_BYTES + A_BYTES);

        #pragma unroll
        for (int ks = 0; ks < 4; ++ks) {
            wmma::fragment<wmma::matrix_a, 16, 16, 16, bf16, wmma::row_major> af[4];
            wmma::fragment<wmma::matrix_b, 16, 16, 16, bf16, wmma::row_major> bfm[2];
            #pragma unroll
            for (int i = 0; i < 4; i++)
                wmma::load_matrix_sync(af[i], As + (wr * 64 + i * 16) * ASTR + ks * 16, ASTR);
            #pragma unroll
            for (int j = 0; j < 2; j++)
                wmma::load_matrix_sync(bfm[j], Bs + (ks * 16) * BSTR + wc * 32 + j * 16, BSTR);
            #pragma unroll
            for (int i = 0; i < 4; i++)
                #pragma unroll
                for (int j = 0; j < 2; j++)
                    wmma::mma_sync(acc[i][j], af[i], bfm[j], acc[i][j]);
        }
        slot  = (slot  + 1 == NST) ? 0 : slot + 1;
        lslot = (lslot + 1 == NST) ? 0 : lslot + 1;
    }
    __syncthreads();   // all warps done reading stage smem before Cs overwrite

    // epilogue via smem
    float* Cs = reinterpret_cast<float*>(smem);
    #pragma unroll
    for (int i = 0; i < 4; i++)
        #pragma unroll
        for (int j = 0; j < 2; j++)
            wmma::store_matrix_sync(Cs + (wr * 64 + i * 16) * CPAD + wc * 32 + j * 16,
                                    acc[i][j], CPAD, wmma::mem_row_major);
    __syncthreads();

    #pragma unroll
    for (int it = 0; it < 16; ++it) {
        int r = wid + it * 8;
        int c = lane * 4;
        int gr = m0 + r, gc = n0 + c;
        if (gr < M) {
            float4 v = *reinterpret_cast<float4*>(Cs + r * CPAD + c);
            float4 bb = *reinterpret_cast<const float4*>(bias + gc);
            v.x += bb.x; v.y += bb.y; v.z += bb.z; v.w += bb.w;
            if (MODE == 1) {
                float4 rr = *reinterpret_cast<const float4*>(res + (size_t)gr * N + gc);
                float4 lv = *reinterpret_cast<const float4*>(ls + gc);
                v.x = rr.x + lv.x * v.x;
                v.y = rr.y + lv.y * v.y;
                v.z = rr.z + lv.z * v.z;
                v.w = rr.w + lv.w * v.w;
            } else if (MODE == 2) {
                v.x = gelu_exact(v.x);
                v.y = gelu_exact(v.y);
                v.z = gelu_exact(v.z);
                v.w = gelu_exact(v.w);
            }
            store4(C, (size_t)gr * N + gc, v);
        }
    }
}

// ---------------- wmma flash attention, 2 CTAs/SM ----------------
#define SPAD 68
#define APAD2 72
#define SS_BYTES (64*SPAD*4)      /* 17408 */
#define QT_BYTES (64*APAD2*2)     /* 9216  */
#define ATTN_SMEM (2*SS_BYTES + 4*QT_BYTES)   /* 71680; 2 CTAs = 143KB */

__global__ __launch_bounds__(256, 2)
void attn_kernel(int tok_off, int n, const bf16* __restrict__ qkv, bf16* __restrict__ att) {
    extern __shared__ char smem[];
    float* Ss = reinterpret_cast<float*>(smem);
    float* Os = Ss + 64 * SPAD;
    bf16*  Qs = reinterpret_cast<bf16*>(smem + 2 * SS_BYTES);
    bf16*  Ks = Qs + 64 * APAD2;
    bf16*  Vs = Ks + 64 * APAD2;
    bf16*  Ps = Vs + 64 * APAD2;

    int b = blockIdx.z, h = blockIdx.y;
    int q0 = blockIdx.x * 64;
    int base = tok_off + b * n;
    int tid = threadIdx.x, wid = tid >> 5;
    int wr = wid >> 1, wc = wid & 1;

    const bf162 qscale = __halves2bfloat162(__float2bfloat16(0.125f), __float2bfloat16(0.125f));
    #pragma unroll
    for (int k = 0; k < 2; k++) {
        int i = tid + k * 256;
        int row = i >> 3, c8 = i & 7;
        int qr = q0 + row; if (qr >= n) qr = n - 1;
        uint4 u = *reinterpret_cast<const uint4*>(qkv + (size_t)(base + qr) * QKVW + h * DH + c8 * 8);
        bf162* p = reinterpret_cast<bf162*>(&u);
        #pragma unroll
        for (int t = 0; t < 4; t++) p[t] = __hmul2(p[t], qscale);
        *reinterpret_cast<uint4*>(Qs + row * APAD2 + c8 * 8) = u;
    }
    for (int i = tid; i < 64 * SPAD; i += 256) Os[i] = 0.f;

    int rrow = tid >> 2;
    int quad = tid & 3;
    float mrow = -1e30f, lrow = 0.f;

    int nchunks = (n + 63) >> 6;
    for (int kc = 0; kc < nchunks; ++kc) {
        int kbase = kc * 64;
        int kcnt = min(64, n - kbase);
        __syncthreads();
        #pragma unroll
        for (int k = 0; k < 2; k++) {
            int i = tid + k * 256;
            int row = i >> 3, c8 = i & 7;
            int kr = kbase + row; if (kr >= n) kr = n - 1;
            size_t o = (size_t)(base + kr) * QKVW + h * DH + c8 * 8;
            *reinterpret_cast<uint4*>(Ks + row * APAD2 + c8 * 8) =
                *reinterpret_cast<const uint4*>(qkv + DIM + o);
            *reinterpret_cast<uint4*>(Vs + row * APAD2 + c8 * 8) =
                *reinterpret_cast<const uint4*>(qkv + 2 * DIM + o);
        }
        __syncthreads();

        {
            wmma::fragment<wmma::accumulator, 16, 16, 16, float> sacc[2];
            #pragma unroll
            for (int j = 0; j < 2; j++) wmma::fill_fragment(sacc[j], 0.f);
            #pragma unroll
            for (int ks = 0; ks < 4; ++ks) {
                wmma::fragment<wmma::matrix_a, 16, 16, 16, bf16, wmma::row_major> af;
                wmma::load_matrix_sync(af, Qs + (wr * 16) * APAD2 + ks * 16, APAD2);
                #pragma unroll
                for (int j = 0; j < 2; j++) {
                    wmma::fragment<wmma::matrix_b, 16, 16, 16, bf16, wmma::col_major> bfm;
                    wmma::load_matrix_sync(bfm, Ks + (wc * 32 + j * 16) * APAD2 + ks * 16, APAD2);
                    wmma::mma_sync(sacc[j], af, bfm, sacc[j]);
                }
            }
            #pragma unroll
            for (int j = 0; j < 2; j++)
                wmma::store_matrix_sync(Ss + (wr * 16) * SPAD + wc * 32 + j * 16,
                                        sacc[j], SPAD, wmma::mem_row_major);
        }
        __syncthreads();

        {
            float sv[16];
            float* srow = Ss + rrow * SPAD + quad * 16;
            #pragma unroll
            for (int t = 0; t < 4; t++) {
                float4 f = *reinterpret_cast<float4*>(srow + t * 4);
                sv[t*4+0] = f.x; sv[t*4+1] = f.y; sv[t*4+2] = f.z; sv[t*4+3] = f.w;
            }
            float mx = -1e30f;
            #pragma unroll
            for (int t = 0; t < 16; t++) {
                int c = quad * 16 + t;
                if (c >= kcnt) sv[t] = -1e30f;
                mx = fmaxf(mx, sv[t]);
            }
            mx = fmaxf(mx, __shfl_xor_sync(0xffffffffu, mx, 1));
            mx = fmaxf(mx, __shfl_xor_sync(0xffffffffu, mx, 2));
            float mnew = fmaxf(mrow, mx);
            float corr = __expf(mrow - mnew);
            float psum = 0.f;
            bf16 pb[16];
            #pragma unroll
            for (int t = 0; t < 16; t++) {
                float p = __expf(sv[t] - mnew);
                psum += p;
                pb[t] = __float2bfloat16(p);
            }
            psum += __shfl_xor_sync(0xffffffffu, psum, 1);
            psum += __shfl_xor_sync(0xffffffffu, psum, 2);
            lrow = lrow * corr + psum;
            mrow = mnew;
            *reinterpret_cast<uint4*>(Ps + rrow * APAD2 + quad * 16)     = *reinterpret_cast<uint4*>(pb);
            *reinterpret_cast<uint4*>(Ps + rrow * APAD2 + quad * 16 + 8) = *reinterpret_cast<uint4*>(pb + 8);
            float* orow = Os + rrow * SPAD + quad * 16;
            #pragma unroll
            for (int t = 0; t < 4; t++) {
                float4 f = *reinterpret_cast<float4*>(orow + t * 4);
                f.x *= corr; f.y *= corr; f.z *= corr; f.w *= corr;
                *reinterpret_cast<float4*>(orow + t * 4) = f;
            }
        }
        __syncthreads();

        {
            wmma::fragment<wmma::accumulator, 16, 16, 16, float> oacc[2];
            #pragma unroll
            for (int j = 0; j < 2; j++)
                wmma::load_matrix_sync(oacc[j], Os + (wr * 16) * SPAD + wc * 32 + j * 16,
                                       SPAD, wmma::mem_row_major);
            #pragma unroll
            for (int ks = 0; ks < 4; ++ks) {
                wmma::fragment<wmma::matrix_a, 16, 16, 16, bf16, wmma::row_major> af;
                wmma::load_matrix_sync(af, Ps + (wr * 16) * APAD2 + ks * 16, APAD2);
                #pragma unroll
                for (int j = 0; j < 2; j++) {
                    wmma::fragment<wmma::matrix_b, 16, 16, 16, bf16, wmma::row_major> bfm;
                    wmma::load_matrix_sync(bfm, Vs + (ks * 16) * APAD2 + wc * 32 + j * 16, APAD2);
                    wmma::mma_sync(oacc[j], af, bfm, oacc[j]);
                }
            }
            #pragma unroll
            for (int j = 0; j < 2; j++)
                wmma::store_matrix_sync(Os + (wr * 16) * SPAD + wc * 32 + j * 16,
                                        oacc[j], SPAD, wmma::mem_row_major);
        }
    }
    __syncthreads();

    if (q0 + rrow < n) {
        float inv = 1.0f / lrow;
        float* orow = Os + rrow * SPAD + quad * 16;
        bf16 ob[16];
        #pragma unroll
        for (int t = 0; t < 16; t++) ob[t] = __float2bfloat16(orow[t] * inv);
        bf16* dst = att + (size_t)(base + q0 + rrow) * DIM + h * DH + quad * 16;
        *reinterpret_cast<uint4*>(dst)     = *reinterpret_cast<uint4*>(ob);
        *reinterpret_cast<uint4*>(dst + 8) = *reinterpret_cast<uint4*>(ob + 8);
    }
}

// ---------------- host launcher ----------------
extern "C" void kernel_launch(void* const* d_in, const int* in_sizes, int n_in,
                              void* d_out, int out_size) {
    const float* x0     = (const float*)d_in[0];
    const float* x1     = (const float*)d_in[1];
    const float* ln1_g  = (const float*)d_in[2];
    const float* ln1_b  = (const float*)d_in[3];
    const float* qkv_w  = (const float*)d_in[4];
    const float* qkv_b  = (const float*)d_in[5];
    const float* proj_w = (const float*)d_in[6];
    const float* proj_b = (const float*)d_in[7];
    const float* ls1    = (const float*)d_in[8];
    const float* ln2_g  = (const float*)d_in[9];
    const float* ln2_b  = (const float*)d_in[10];
    const float* fc1_w  = (const float*)d_in[11];
    const float* fc1_b  = (const float*)d_in[12];
    const float* fc2_w  = (const float*)d_in[13];
    const float* fc2_b  = (const float*)d_in[14];
    const float* ls2    = (const float*)d_in[15];
    float* out = (float*)d_out;

    float *px, *ph;
    bf16 *plnx, *pqkv, *patt, *pln2, *pfc1;
    bf16 *pqkvw, *pprojw, *pfc1w, *pfc2w;
    cudaGetSymbolAddress((void**)&px,    g_x);
    cudaGetSymbolAddress((void**)&ph,    g_h);
    cudaGetSymbolAddress((void**)&plnx,  g_lnx);
    cudaGetSymbolAddress((void**)&pqkv,  g_qkv);
    cudaGetSymbolAddress((void**)&patt,  g_att);
    cudaGetSymbolAddress((void**)&pln2,  g_ln2);
    cudaGetSymbolAddress((void**)&pfc1,  g_fc1);
    cudaGetSymbolAddress((void**)&pqkvw, g_qkvw);
    cudaGetSymbolAddress((void**)&pprojw,g_projw);
    cudaGetSymbolAddress((void**)&pfc1w, g_fc1w);
    cudaGetSymbolAddress((void**)&pfc2w, g_fc2w);

    cudaFuncSetAttribute(gemm_kernel<0,bf16>,  cudaFuncAttributeMaxDynamicSharedMemorySize, GEMM_SMEM);
    cudaFuncSetAttribute(gemm_kernel<1,float>, cudaFuncAttributeMaxDynamicSharedMemorySize, GEMM_SMEM);
    cudaFuncSetAttribute(gemm_kernel<2,bf16>,  cudaFuncAttributeMaxDynamicSharedMemorySize, GEMM_SMEM);
    cudaFuncSetAttribute(attn_kernel,          cudaFuncAttributeMaxDynamicSharedMemorySize, ATTN_SMEM);

    const int mtiles = (TTOT + BM - 1) / BM;  // 59

    // 1. convert all weights (one launch) + fused pack+LN1
    cvt_all_kernel<<<(CVT_S3 + 255) / 256, 256>>>(qkv_w, proj_w, fc1_w, fc2_w);
    ln_kernel<1><<<TTOT, 256>>>(x0, x1, ln1_g, ln1_b, px, plnx);
    // 2. QKV gemm (bf16 out)
    gemm_kernel<0,bf16><<<dim3(mtiles, QKVW / BN), 256, GEMM_SMEM>>>(
        plnx, pqkvw, qkv_b, nullptr, nullptr, pqkv, TTOT, QKVW, DIM);
    // 3. attention
    attn_kernel<<<dim3((T0N + 63) / 64, NH, T0B), 256, ATTN_SMEM>>>(0, T0N, pqkv, patt);
    attn_kernel<<<dim3((T1N + 63) / 64, NH, T1B), 256, ATTN_SMEM>>>(T0B * T0N, T1N, pqkv, patt);
    // 4. proj + residual -> h (fp32)
    gemm_kernel<1,float><<<dim3(mtiles, DIM / BN), 256, GEMM_SMEM>>>(
        patt, pprojw, proj_b, px, ls1, ph, TTOT, DIM, DIM);
    // 5. LN2 -> bf16
    ln_kernel<0><<<TTOT, 256>>>(ph, nullptr, ln2_g, ln2_b, nullptr, pln2);
    // 6. fc1 + gelu (bf16 out)
    gemm_kernel<2,bf16><<<dim3(mtiles, HID / BN), 256, GEMM_SMEM>>>(
        pln2, pfc1w, fc1_b, nullptr, nullptr, pfc1, TTOT, HID, DIM);
    // 7. fc2 + residual -> out (fp32)
    gemm_kernel<1,float><<<dim3(mtiles, DIM / BN), 256, GEMM_SMEM>>>(
        pfc1, pfc2w, fc2_b, ph, ls2, out, TTOT, DIM, HID);
}

// round 6
// speedup vs baseline: 4.3332x; 1.2876x over previous
#include <cuda_runtime.h>
#include <cuda_bf16.h>
#include <mma.h>
#include <math.h>
#include <stdint.h>

using namespace nvcuda;

#define T0B 4
#define T0N 1370
#define T1B 8
#define T1N 257
#define TTOT (T0B*T0N + T1B*T1N)   /* 7536 */
#define DIM 1024
#define NH 16
#define DH 64
#define HID 4096
#define QKVW (3*DIM)

typedef __nv_bfloat16 bf16;
typedef __nv_bfloat162 bf162;

// ---------------- scratch (static device globals; no allocation) ----------------
__device__ float g_x[TTOT*DIM];                    // packed input (residual 1)
__device__ float g_h[TTOT*DIM];                    // residual 2
__device__ bf16  g_lnx[TTOT*DIM];
__device__ bf16  g_qkv[(size_t)TTOT*QKVW];
__device__ bf16  g_att[TTOT*DIM];
__device__ bf16  g_ln2[TTOT*DIM];
__device__ bf16  g_fc1[(size_t)TTOT*HID];
__device__ bf16  g_qkvw[DIM*QKVW];
__device__ bf16  g_projw[DIM*DIM];
__device__ bf16  g_fc1w[DIM*HID];
__device__ bf16  g_fc2w[HID*DIM];

// ---------------- helpers ----------------
__device__ __forceinline__ float gelu_exact(float x) {
    return 0.5f * x * (1.0f + erff(x * 0.70710678118654752f));
}
__device__ __forceinline__ unsigned smem_u32(const void* p) {
    return (unsigned)__cvta_generic_to_shared(p);
}
#define CP_ASYNC16(dst, src) \
    asm volatile("cp.async.cg.shared.global [%0], [%1], 16;\n" :: "r"(dst), "l"(src))
#define CP_COMMIT() asm volatile("cp.async.commit_group;\n" ::: "memory")
#define CP_WAIT(N)  asm volatile("cp.async.wait_group %0;\n" :: "n"(N) : "memory")

__device__ __forceinline__ void store4(float* C, size_t idx, float4 v) {
    *reinterpret_cast<float4*>(C + idx) = v;
}
__device__ __forceinline__ void store4(bf16* C, size_t idx, float4 v) {
    bf162 lo = __halves2bfloat162(__float2bfloat16(v.x), __float2bfloat16(v.y));
    bf162 hi = __halves2bfloat162(__float2bfloat16(v.z), __float2bfloat16(v.w));
    uint2 u;
    u.x = *reinterpret_cast<unsigned*>(&lo);
    u.y = *reinterpret_cast<unsigned*>(&hi);
    *reinterpret_cast<uint2*>(C + idx) = u;
}

// mma.sync m16n8k16 bf16 -> f32
__device__ __forceinline__ void mma16816(float c[4], const uint32_t a[4],
                                         uint32_t b0, uint32_t b1) {
    asm volatile("mma.sync.aligned.m16n8k16.row.col.f32.bf16.bf16.f32 "
                 "{%0,%1,%2,%3}, {%4,%5,%6,%7}, {%8,%9}, {%0,%1,%2,%3};"
                 : "+f"(c[0]), "+f"(c[1]), "+f"(c[2]), "+f"(c[3])
                 : "r"(a[0]), "r"(a[1]), "r"(a[2]), "r"(a[3]), "r"(b0), "r"(b1));
}
__device__ __forceinline__ void ldsm_x4(uint32_t& r0, uint32_t& r1, uint32_t& r2,
                                        uint32_t& r3, uint32_t a) {
    asm volatile("ldmatrix.sync.aligned.m8n8.x4.shared.b16 {%0,%1,%2,%3}, [%4];"
                 : "=r"(r0), "=r"(r1), "=r"(r2), "=r"(r3) : "r"(a));
}
__device__ __forceinline__ void ldsm_x4t(uint32_t& r0, uint32_t& r1, uint32_t& r2,
                                         uint32_t& r3, uint32_t a) {
    asm volatile("ldmatrix.sync.aligned.m8n8.x4.trans.shared.b16 {%0,%1,%2,%3}, [%4];"
                 : "=r"(r0), "=r"(r1), "=r"(r2), "=r"(r3) : "r"(a));
}
__device__ __forceinline__ uint32_t pack_bf2(float x, float y) {
    bf162 t = __floats2bfloat162_rn(x, y);
    return *reinterpret_cast<uint32_t*>(&t);
}

// ---------------- all-weights f32 -> bf16 convert (one launch) ----------------
#define CVT_S0 (DIM*QKVW/4)
#define CVT_S1 (CVT_S0 + DIM*DIM/4)
#define CVT_S2 (CVT_S1 + DIM*HID/4)
#define CVT_S3 (CVT_S2 + HID*DIM/4)
__global__ void cvt_all_kernel(const float* __restrict__ w0, const float* __restrict__ w1,
                               const float* __restrict__ w2, const float* __restrict__ w3) {
    int i = blockIdx.x * 256 + threadIdx.x;
    if (i >= CVT_S3) return;
    const float* src; bf16* dst; int off;
    if (i < CVT_S0)      { src = w0; dst = g_qkvw;  off = i; }
    else if (i < CVT_S1) { src = w1; dst = g_projw; off = i - CVT_S0; }
    else if (i < CVT_S2) { src = w2; dst = g_fc1w;  off = i - CVT_S1; }
    else                 { src = w3; dst = g_fc2w;  off = i - CVT_S2; }
    float4 v = reinterpret_cast<const float4*>(src)[off];
    store4(dst, (size_t)off * 4, v);
}

// ---------------- layernorm (PACK=1 fuses ragged pack) ----------------
template<int PACK>
__global__ void ln_kernel(const float* __restrict__ in0, const float* __restrict__ in1,
                          const float* __restrict__ gw, const float* __restrict__ bw,
                          float* __restrict__ xout, bf16* __restrict__ out) {
    int row = blockIdx.x;
    int tid = threadIdx.x;
    const float* src;
    if (PACK) {
        const int split = T0B * T0N;
        src = (row < split) ? in0 + (size_t)row * DIM
                            : in1 + (size_t)(row - split) * DIM;
    } else {
        src = in0 + (size_t)row * DIM;
    }
    const float4 v = reinterpret_cast<const float4*>(src)[tid];
    if (PACK)
        reinterpret_cast<float4*>(xout + (size_t)row * DIM)[tid] = v;
    float s  = v.x + v.y + v.z + v.w;
    float s2 = v.x*v.x + v.y*v.y + v.z*v.z + v.w*v.w;
    #pragma unroll
    for (int o = 16; o; o >>= 1) {
        s  += __shfl_down_sync(0xffffffffu, s,  o);
        s2 += __shfl_down_sync(0xffffffffu, s2, o);
    }
    __shared__ float ss[8], ss2[8];
    __shared__ float mb, rb;
    int w = tid >> 5, l = tid & 31;
    if (l == 0) { ss[w] = s; ss2[w] = s2; }
    __syncthreads();
    if (tid == 0) {
        float a = 0.f, a2 = 0.f;
        #pragma unroll
        for (int i = 0; i < 8; i++) { a += ss[i]; a2 += ss2[i]; }
        float m = a * (1.0f / DIM);
        float var = a2 * (1.0f / DIM) - m * m;
        mb = m;
        rb = rsqrtf(var + 1e-5f);
    }
    __syncthreads();
    float m = mb, r = rb;
    float4 g4 = reinterpret_cast<const float4*>(gw)[tid];
    float4 b4 = reinterpret_cast<const float4*>(bw)[tid];
    float4 o;
    o.x = (v.x - m) * r * g4.x + b4.x;
    o.y = (v.y - m) * r * g4.y + b4.y;
    o.z = (v.z - m) * r * g4.z + b4.z;
    o.w = (v.w - m) * r * g4.w + b4.w;
    store4(out, (size_t)row * DIM + tid * 4, o);
}

// ---------------- bf16 wmma GEMM, 3-stage cp.async (unchanged round 5) ----------------
#define BM 128
#define BN 128
#define BK 64
#define ASTR 72
#define BSTR 136
#define A_BYTES (BM*ASTR*2)
#define B_BYTES (BK*BSTR*2)
#define STAGE_BYTES (A_BYTES + B_BYTES)
#define NST 3
#define CPAD 132
#define GEMM_SMEM (NST*STAGE_BYTES)

template<int MODE, typename OT>
__global__ __launch_bounds__(256, 2)
void gemm_kernel(const bf16* __restrict__ A, const bf16* __restrict__ B,
                 const float* __restrict__ bias, const float* __restrict__ res,
                 const float* __restrict__ ls, OT* __restrict__ C,
                 int M, int N, int K) {
    extern __shared__ char smem[];
    int tid = threadIdx.x;
    int wid = tid >> 5, lane = tid & 31;
    int m0 = blockIdx.x * BM, n0 = blockIdx.y * BN;
    int wr = wid >> 2, wc = wid & 3;

    wmma::fragment<wmma::accumulator, 16, 16, 16, float> acc[4][2];
    #pragma unroll
    for (int i = 0; i < 4; i++)
        #pragma unroll
        for (int j = 0; j < 2; j++)
            wmma::fill_fragment(acc[i][j], 0.0f);

    int nk = K / BK;

    auto load_stage = [&](int kt, int slot) {
        char* As = smem + slot * STAGE_BYTES;
        char* Bs = As + A_BYTES;
        #pragma unroll
        for (int k = 0; k < 4; k++) {
            int i = tid + k * 256;
            int row = i >> 3, c8 = i & 7;
            int grow = m0 + row; if (grow >= M) grow = M - 1;
            const bf16* src = A + (size_t)grow * K + kt * BK + c8 * 8;
            unsigned dst = smem_u32(As + row * (ASTR * 2) + c8 * 16);
            CP_ASYNC16(dst, src);
        }
        #pragma unroll
        for (int k = 0; k < 4; k++) {
            int i = tid + k * 256;
            int row = i >> 4, c8 = i & 15;
            const bf16* src = B + (size_t)(kt * BK + row) * N + n0 + c8 * 8;
            unsigned dst = smem_u32(Bs + row * (BSTR * 2) + c8 * 16);
            CP_ASYNC16(dst, src);
        }
    };

    load_stage(0, 0); CP_COMMIT();
    if (nk > 1) { load_stage(1, 1); CP_COMMIT(); } else { CP_COMMIT(); }

    int slot = 0, lslot = 2 % NST;
    for (int kt = 0; kt < nk; ++kt) {
        CP_WAIT(1);
        __syncthreads();
        if (kt + 2 < nk) load_stage(kt + 2, lslot);
        CP_COMMIT();

        bf16* As = reinterpret_cast<bf16*>(smem + slot * STAGE_BYTES);
        bf16* Bs = reinterpret_cast<bf16*>(smem + slot * STAGE_BYTES + A_BYTES);

        #pragma unroll
        for (int ks = 0; ks < 4; ++ks) {
            wmma::fragment<wmma::matrix_a, 16, 16, 16, bf16, wmma::row_major> af[4];
            wmma::fragment<wmma::matrix_b, 16, 16, 16, bf16, wmma::row_major> bfm[2];
            #pragma unroll
            for (int i = 0; i < 4; i++)
                wmma::load_matrix_sync(af[i], As + (wr * 64 + i * 16) * ASTR + ks * 16, ASTR);
            #pragma unroll
            for (int j = 0; j < 2; j++)
                wmma::load_matrix_sync(bfm[j], Bs + (ks * 16) * BSTR + wc * 32 + j * 16, BSTR);
            #pragma unroll
            for (int i = 0; i < 4; i++)
                #pragma unroll
                for (int j = 0; j < 2; j++)
                    wmma::mma_sync(acc[i][j], af[i], bfm[j], acc[i][j]);
        }
        slot  = (slot  + 1 == NST) ? 0 : slot + 1;
        lslot = (lslot + 1 == NST) ? 0 : lslot + 1;
    }
    __syncthreads();

    float* Cs = reinterpret_cast<float*>(smem);
    #pragma unroll
    for (int i = 0; i < 4; i++)
        #pragma unroll
        for (int j = 0; j < 2; j++)
            wmma::store_matrix_sync(Cs + (wr * 64 + i * 16) * CPAD + wc * 32 + j * 16,
                                    acc[i][j], CPAD, wmma::mem_row_major);
    __syncthreads();

    #pragma unroll
    for (int it = 0; it < 16; ++it) {
        int r = wid + it * 8;
        int c = lane * 4;
        int gr = m0 + r, gc = n0 + c;
        if (gr < M) {
            float4 v = *reinterpret_cast<float4*>(Cs + r * CPAD + c);
            float4 bb = *reinterpret_cast<const float4*>(bias + gc);
            v.x += bb.x; v.y += bb.y; v.z += bb.z; v.w += bb.w;
            if (MODE == 1) {
                float4 rr = *reinterpret_cast<const float4*>(res + (size_t)gr * N + gc);
                float4 lv = *reinterpret_cast<const float4*>(ls + gc);
                v.x = rr.x + lv.x * v.x;
                v.y = rr.y + lv.y * v.y;
                v.z = rr.z + lv.z * v.z;
                v.w = rr.w + lv.w * v.w;
            } else if (MODE == 2) {
                v.x = gelu_exact(v.x);
                v.y = gelu_exact(v.y);
                v.z = gelu_exact(v.z);
                v.w = gelu_exact(v.w);
            }
            store4(C, (size_t)gr * N + gc, v);
        }
    }
}

// ---------------- FA2-style register-resident attention ----------------
// 128 threads / 4 warps; warp w owns q-rows w*16..w*16+15; 64-key chunks.
// smem: 3 stages x (K 64x72bf16 + V 64x72bf16) + Q/O staging 64x72bf16.
#define AT_STR 144            /* bytes per row: 72 bf16 */
#define AT_KV  (64*AT_STR)    /* 9216 per matrix */
#define AT_STAGE (2*AT_KV)    /* 18432 */
#define AT_QOFF (3*AT_STAGE)  /* 55296 */
#define ATTN_SMEM (AT_QOFF + 64*AT_STR)  /* 64512; x3 CTAs = 193.5KB */

__global__ __launch_bounds__(128, 3)
void attn_kernel(int tok_off, int n, const bf16* __restrict__ qkv, bf16* __restrict__ att) {
    extern __shared__ char smem[];
    uint32_t sb = smem_u32(smem);
    const int tid = threadIdx.x, lane = tid & 31, w = tid >> 5;
    const int b = blockIdx.z, h = blockIdx.y;
    const int q0 = blockIdx.x * 64;
    const int base = tok_off + b * n;
    const int r8 = lane & 7, sub = lane >> 3;
    const int quad = lane & 3, hrow = lane >> 2;

    // Q tile -> smem (cp.async)
    #pragma unroll
    for (int t = 0; t < 4; t++) {
        int i = tid + t * 128;
        int row = i >> 3, c = i & 7;
        int qr = q0 + row; if (qr >= n) qr = n - 1;
        CP_ASYNC16(sb + AT_QOFF + row * AT_STR + c * 16,
                   qkv + (size_t)(base + qr) * QKVW + h * DH + c * 8);
    }
    CP_COMMIT();

    int nch = (n + 63) >> 6;
    auto load_kv = [&](int kc, int slot) {
        uint32_t st = sb + slot * AT_STAGE;
        #pragma unroll
        for (int t = 0; t < 4; t++) {
            int i = tid + t * 128;
            int row = i >> 3, c = i & 7;
            int kr = kc * 64 + row; if (kr >= n) kr = n - 1;
            size_t o = (size_t)(base + kr) * QKVW + h * DH + c * 8;
            CP_ASYNC16(st + row * AT_STR + c * 16,         qkv + DIM + o);
            CP_ASYNC16(st + AT_KV + row * AT_STR + c * 16, qkv + 2 * DIM + o);
        }
    };
    load_kv(0, 0); CP_COMMIT();
    if (nch > 1) load_kv(1, 1);
    CP_COMMIT();

    CP_WAIT(2);
    __syncthreads();

    // Q fragments (held all kernel)
    uint32_t qf[4][4];
    {
        uint32_t qrow = sb + AT_QOFF + (w * 16 + (lane & 15)) * AT_STR;
        #pragma unroll
        for (int kt = 0; kt < 4; kt++)
            ldsm_x4(qf[kt][0], qf[kt][1], qf[kt][2], qf[kt][3],
                    qrow + (kt * 16 + (lane >> 4) * 8) * 2);
    }

    float o[8][4];
    #pragma unroll
    for (int j = 0; j < 8; j++) { o[j][0] = o[j][1] = o[j][2] = o[j][3] = 0.f; }
    float m0 = -1e30f, m1 = -1e30f, l0 = 0.f, l1 = 0.f;

    for (int kc = 0; kc < nch; ++kc) {
        CP_WAIT(1);
        __syncthreads();
        if (kc + 2 < nch) load_kv(kc + 2, (kc + 2) % 3);
        CP_COMMIT();

        int slot = kc % 3;
        uint32_t kb = sb + slot * AT_STAGE;
        uint32_t vb = kb + AT_KV;

        // S = Q K^T
        float s[8][4];
        #pragma unroll
        for (int j = 0; j < 8; j++) {
            s[j][0] = s[j][1] = s[j][2] = s[j][3] = 0.f;
            uint32_t krow = kb + (j * 8 + r8) * AT_STR;
            #pragma unroll
            for (int kt2 = 0; kt2 < 2; kt2++) {
                uint32_t b0, b1, b2, b3;
                ldsm_x4(b0, b1, b2, b3, krow + (kt2 * 32 + sub * 8) * 2);
                mma16816(s[j], qf[kt2 * 2],     b0, b1);
                mma16816(s[j], qf[kt2 * 2 + 1], b2, b3);
            }
        }

        // softmax in registers
        int kbase = kc * 64;
        bool tail = (kbase + 64 > n);
        float mx0 = -1e30f, mx1 = -1e30f;
        #pragma unroll
        for (int j = 0; j < 8; j++) {
            s[j][0] *= 0.125f; s[j][1] *= 0.125f; s[j][2] *= 0.125f; s[j][3] *= 0.125f;
            if (tail) {
                int c0 = kbase + j * 8 + quad * 2;
                if (c0 >= n)     { s[j][0] = -1e30f; s[j][2] = -1e30f; }
                if (c0 + 1 >= n) { s[j][1] = -1e30f; s[j][3] = -1e30f; }
            }
            mx0 = fmaxf(mx0, fmaxf(s[j][0], s[j][1]));
            mx1 = fmaxf(mx1, fmaxf(s[j][2], s[j][3]));
        }
        mx0 = fmaxf(mx0, __shfl_xor_sync(0xffffffffu, mx0, 1));
        mx0 = fmaxf(mx0, __shfl_xor_sync(0xffffffffu, mx0, 2));
        mx1 = fmaxf(mx1, __shfl_xor_sync(0xffffffffu, mx1, 1));
        mx1 = fmaxf(mx1, __shfl_xor_sync(0xffffffffu, mx1, 2));
        float mn0 = fmaxf(m0, mx0), mn1 = fmaxf(m1, mx1);
        float cr0 = __expf(m0 - mn0), cr1 = __expf(m1 - mn1);
        m0 = mn0; m1 = mn1;

        float sum0 = 0.f, sum1 = 0.f;
        #pragma unroll
        for (int j = 0; j < 8; j++) {
            s[j][0] = __expf(s[j][0] - mn0); s[j][1] = __expf(s[j][1] - mn0);
            s[j][2] = __expf(s[j][2] - mn1); s[j][3] = __expf(s[j][3] - mn1);
            sum0 += s[j][0] + s[j][1];
            sum1 += s[j][2] + s[j][3];
        }
        sum0 += __shfl_xor_sync(0xffffffffu, sum0, 1);
        sum0 += __shfl_xor_sync(0xffffffffu, sum0, 2);
        sum1 += __shfl_xor_sync(0xffffffffu, sum1, 1);
        sum1 += __shfl_xor_sync(0xffffffffu, sum1, 2);
        l0 = l0 * cr0 + sum0;
        l1 = l1 * cr1 + sum1;

        // P -> A fragments (register repack)
        uint32_t a[4][4];
        #pragma unroll
        for (int t = 0; t < 4; t++) {
            a[t][0] = pack_bf2(s[2*t][0],   s[2*t][1]);
            a[t][1] = pack_bf2(s[2*t][2],   s[2*t][3]);
            a[t][2] = pack_bf2(s[2*t+1][0], s[2*t+1][1]);
            a[t][3] = pack_bf2(s[2*t+1][2], s[2*t+1][3]);
        }

        // rescale O
        #pragma unroll
        for (int j = 0; j < 8; j++) {
            o[j][0] *= cr0; o[j][1] *= cr0; o[j][2] *= cr1; o[j][3] *= cr1;
        }

        // O += P V
        #pragma unroll
        for (int t = 0; t < 4; t++) {
            #pragma unroll
            for (int j2 = 0; j2 < 4; j2++) {
                uint32_t b0, b1, b2, b3;
                uint32_t addr = vb + (t * 16 + (sub & 1) * 8 + r8) * AT_STR
                                   + (j2 * 16 + (sub >> 1) * 8) * 2;
                ldsm_x4t(b0, b1, b2, b3, addr);
                mma16816(o[2*j2],     a[t], b0, b1);
                mma16816(o[2*j2+1],   a[t], b2, b3);
            }
        }
    }

    // output: stage to smem (reuse Q region, per-warp), coalesced write
    float inv0 = 1.0f / l0, inv1 = 1.0f / l1;
    uint32_t wbase = sb + AT_QOFF + (w * 16) * AT_STR;
    uint32_t row0 = wbase + hrow * AT_STR;
    #pragma unroll
    for (int j = 0; j < 8; j++) {
        uint32_t v0 = pack_bf2(o[j][0] * inv0, o[j][1] * inv0);
        uint32_t v1 = pack_bf2(o[j][2] * inv1, o[j][3] * inv1);
        asm volatile("st.shared.b32 [%0], %1;" :: "r"(row0 + (j * 8 + quad * 2) * 2), "r"(v0));
        asm volatile("st.shared.b32 [%0], %1;" :: "r"(row0 + 8 * AT_STR + (j * 8 + quad * 2) * 2), "r"(v1));
    }
    __syncwarp();
    #pragma unroll
    for (int t = 0; t < 4; t++) {
        int i = lane + t * 32;
        int row = i >> 3, c = i & 7;
        int qr = q0 + w * 16 + row;
        if (qr < n) {
            uint4 u;
            asm volatile("ld.shared.v4.b32 {%0,%1,%2,%3}, [%4];"
                         : "=r"(u.x), "=r"(u.y), "=r"(u.z), "=r"(u.w)
                         : "r"(wbase + row * AT_STR + c * 16));
            *reinterpret_cast<uint4*>(att + (size_t)(base + qr) * DIM + h * DH + c * 8) = u;
        }
    }
}

// ---------------- host launcher ----------------
extern "C" void kernel_launch(void* const* d_in, const int* in_sizes, int n_in,
                              void* d_out, int out_size) {
    const float* x0     = (const float*)d_in[0];
    const float* x1     = (const float*)d_in[1];
    const float* ln1_g  = (const float*)d_in[2];
    const float* ln1_b  = (const float*)d_in[3];
    const float* qkv_w  = (const float*)d_in[4];
    const float* qkv_b  = (const float*)d_in[5];
    const float* proj_w = (const float*)d_in[6];
    const float* proj_b = (const float*)d_in[7];
    const float* ls1    = (const float*)d_in[8];
    const float* ln2_g  = (const float*)d_in[9];
    const float* ln2_b  = (const float*)d_in[10];
    const float* fc1_w  = (const float*)d_in[11];
    const float* fc1_b  = (const float*)d_in[12];
    const float* fc2_w  = (const float*)d_in[13];
    const float* fc2_b  = (const float*)d_in[14];
    const float* ls2    = (const float*)d_in[15];
    float* out = (float*)d_out;

    float *px, *ph;
    bf16 *plnx, *pqkv, *patt, *pln2, *pfc1;
    bf16 *pqkvw, *pprojw, *pfc1w, *pfc2w;
    cudaGetSymbolAddress((void**)&px,    g_x);
    cudaGetSymbolAddress((void**)&ph,    g_h);
    cudaGetSymbolAddress((void**)&plnx,  g_lnx);
    cudaGetSymbolAddress((void**)&pqkv,  g_qkv);
    cudaGetSymbolAddress((void**)&patt,  g_att);
    cudaGetSymbolAddress((void**)&pln2,  g_ln2);
    cudaGetSymbolAddress((void**)&pfc1,  g_fc1);
    cudaGetSymbolAddress((void**)&pqkvw, g_qkvw);
    cudaGetSymbolAddress((void**)&pprojw,g_projw);
    cudaGetSymbolAddress((void**)&pfc1w, g_fc1w);
    cudaGetSymbolAddress((void**)&pfc2w, g_fc2w);

    cudaFuncSetAttribute(gemm_kernel<0,bf16>,  cudaFuncAttributeMaxDynamicSharedMemorySize, GEMM_SMEM);
    cudaFuncSetAttribute(gemm_kernel<1,float>, cudaFuncAttributeMaxDynamicSharedMemorySize, GEMM_SMEM);
    cudaFuncSetAttribute(gemm_kernel<2,bf16>,  cudaFuncAttributeMaxDynamicSharedMemorySize, GEMM_SMEM);
    cudaFuncSetAttribute(attn_kernel,          cudaFuncAttributeMaxDynamicSharedMemorySize, ATTN_SMEM);

    const int mtiles = (TTOT + BM - 1) / BM;  // 59

    // 1. convert all weights + fused pack+LN1
    cvt_all_kernel<<<(CVT_S3 + 255) / 256, 256>>>(qkv_w, proj_w, fc1_w, fc2_w);
    ln_kernel<1><<<TTOT, 256>>>(x0, x1, ln1_g, ln1_b, px, plnx);
    // 2. QKV gemm
    gemm_kernel<0,bf16><<<dim3(mtiles, QKVW / BN), 256, GEMM_SMEM>>>(
        plnx, pqkvw, qkv_b, nullptr, nullptr, pqkv, TTOT, QKVW, DIM);
    // 3. attention (register-resident FA2)
    attn_kernel<<<dim3((T0N + 63) / 64, NH, T0B), 128, ATTN_SMEM>>>(0, T0N, pqkv, patt);
    attn_kernel<<<dim3((T1N + 63) / 64, NH, T1B), 128, ATTN_SMEM>>>(T0B * T0N, T1N, pqkv, patt);
    // 4. proj + residual -> h (fp32)
    gemm_kernel<1,float><<<dim3(mtiles, DIM / BN), 256, GEMM_SMEM>>>(
        patt, pprojw, proj_b, px, ls1, ph, TTOT, DIM, DIM);
    // 5. LN2 -> bf16
    ln_kernel<0><<<TTOT, 256>>>(ph, nullptr, ln2_g, ln2_b, nullptr, pln2);
    // 6. fc1 + gelu
    gemm_kernel<2,bf16><<<dim3(mtiles, HID / BN), 256, GEMM_SMEM>>>(
        pln2, pfc1w, fc1_b, nullptr, nullptr, pfc1, TTOT, HID, DIM);
    // 7. fc2 + residual -> out
    gemm_kernel<1,float><<<dim3(mtiles, DIM / BN), 256, GEMM_SMEM>>>(
        pfc1, pfc2w, fc2_b, ph, ls2, out, TTOT, DIM, HID);
}